// round 2
// baseline (speedup 1.0000x reference)
#include <cuda_runtime.h>

namespace {
constexpr int Bb = 32, Cc = 64, Tt = 64, Vv = 325;
constexpr int TPB = 256;
constexpr int GW  = 80;   // gso staging chunk width (325 = 4*80 + 5)

// SMEM layout in floats
constexpr int XS_OFF = 0;                    // Xs[C][V]  = 20800
constexpr int US_OFF = XS_OFF + Cc * Vv;     // Us[V][C]  = 20800 (stride 64, float4-aligned)
constexpr int W0_OFF = US_OFF + Vv * Cc;     // W0'[C][C] = 4096
constexpr int W1_OFF = W0_OFF + Cc * Cc;     // W1 [C][C] = 4096
constexpr int BS_OFF = W1_OFF + Cc * Cc;     // bias      = 64
constexpr int GS_OFF = BS_OFF + Cc;          // Gs[64][GW]=5120 ; reused as Os[64][65]=4160
constexpr int SMEM_FLOATS = GS_OFF + 64 * GW;
constexpr int SMEM_BYTES  = SMEM_FLOATS * 4; // ~214.8 KB
}

__global__ void __launch_bounds__(TPB, 1)
gconv_kernel(const float* __restrict__ x, const float* __restrict__ gso,
             const float* __restrict__ weight, const float* __restrict__ bias,
             float* __restrict__ out)
{
    extern __shared__ float sm[];
    float* Xs  = sm + XS_OFF;   // [C][V]   Xs[i*V + v] = x[b,i,t,v]
    float* Us  = sm + US_OFF;   // [V][C]   U = X @ W1
    float* W0p = sm + W0_OFF;   // W0 + I
    float* W1s = sm + W1_OFF;
    float* bs  = sm + BS_OFF;
    float* Gs  = sm + GS_OFF;   // gso staging; later reused as Os[c][65]

    const int bt  = blockIdx.x;
    const int b   = bt >> 6;
    const int t   = bt & 63;
    const int tid = threadIdx.x;

    // ---- load weights (+ fold identity for residual) ----
    for (int idx = tid; idx < Cc * Cc; idx += TPB) {
        int i = idx >> 6, j = idx & 63;
        W0p[idx] = weight[idx] + (i == j ? 1.0f : 0.0f);
        W1s[idx] = weight[Cc * Cc + idx];
    }
    if (tid < Cc) bs[tid] = bias[tid];

    // ---- load X: straight strided copy, coalesced ----
    const float* xb = x + ((size_t)(b * Cc) * Tt + t) * Vv;
    for (int idx = tid; idx < Cc * Vv; idx += TPB) {
        int i = idx / Vv, v = idx - i * Vv;
        Xs[idx] = xb[(size_t)i * Tt * Vv + v];
    }
    __syncthreads();

    const int cg = tid & 15;        // c-group: c0..c0+3
    const int vq = tid >> 4;        // 0..15, 4 v's each -> 64 v per pass
    const int c0 = cg * 4;

    // ---- U[v][c] = sum_i Xs[i][v] * W1[i][c] ----
    for (int vbase = 0; vbase < Vv; vbase += 64) {
        const int v0 = vbase + vq * 4;
        float acc[4][4] = {};
        #pragma unroll 8
        for (int i = 0; i < Cc; i++) {
            float4 wv = *(const float4*)&W1s[i * Cc + c0];
            #pragma unroll
            for (int j = 0; j < 4; j++) {
                float xv = Xs[i * Vv + v0 + j];   // may read garbage past V; stores guarded
                acc[j][0] += xv * wv.x; acc[j][1] += xv * wv.y;
                acc[j][2] += xv * wv.z; acc[j][3] += xv * wv.w;
            }
        }
        #pragma unroll
        for (int j = 0; j < 4; j++) {
            int v = v0 + j;
            if (v < Vv)
                *(float4*)&Us[v * Cc + c0] =
                    make_float4(acc[j][0], acc[j][1], acc[j][2], acc[j][3]);
        }
    }
    __syncthreads();

    // ---- out[v][c] = bias + X@W0' + gso @ U ----
    float* ob = out + ((size_t)(b * Cc) * Tt + t) * Vv;

    for (int vbase = 0; vbase < Vv; vbase += 64) {
        const int v0 = vbase + vq * 4;
        float acc[4][4];
        float4 bv = *(const float4*)&bs[c0];
        #pragma unroll
        for (int j = 0; j < 4; j++) {
            acc[j][0] = bv.x; acc[j][1] = bv.y; acc[j][2] = bv.z; acc[j][3] = bv.w;
        }

        // channel-mix part: + X @ W0'
        #pragma unroll 8
        for (int i = 0; i < Cc; i++) {
            float4 wv = *(const float4*)&W0p[i * Cc + c0];
            #pragma unroll
            for (int j = 0; j < 4; j++) {
                float xv = Xs[i * Vv + v0 + j];
                acc[j][0] += xv * wv.x; acc[j][1] += xv * wv.y;
                acc[j][2] += xv * wv.z; acc[j][3] += xv * wv.w;
            }
        }

        // gso part, staged in chunks of GW
        for (int wb = 0; wb < Vv; wb += GW) {
            const int wlen = min(GW, Vv - wb);
            __syncthreads();   // also protects Gs/Os reuse from previous pass
            for (int idx = tid; idx < 64 * GW; idx += TPB) {
                int r = idx / GW, q = idx - r * GW;
                int v = vbase + r;
                Gs[idx] = (v < Vv && q < wlen) ? gso[(size_t)v * Vv + wb + q] : 0.0f;
            }
            __syncthreads();
            #pragma unroll 4
            for (int q = 0; q < wlen; q++) {
                float4 u = *(const float4*)&Us[(wb + q) * Cc + c0];
                #pragma unroll
                for (int j = 0; j < 4; j++) {
                    float g = Gs[(vq * 4 + j) * GW + q];
                    acc[j][0] += g * u.x; acc[j][1] += g * u.y;
                    acc[j][2] += g * u.z; acc[j][3] += g * u.w;
                }
            }
        }

        // epilogue: transpose through SMEM (reuse Gs as Os[c][65]) for coalesced stores
        __syncthreads();
        #pragma unroll
        for (int j = 0; j < 4; j++) {
            int vl = vq * 4 + j;
            #pragma unroll
            for (int k = 0; k < 4; k++)
                Gs[(c0 + k) * 65 + vl] = acc[j][k];   // pad 65 -> conflict-free
        }
        __syncthreads();
        for (int idx = tid; idx < 64 * 64; idx += TPB) {
            int c = idx >> 6, vl = idx & 63;
            int v = vbase + vl;
            if (v < Vv)
                ob[(size_t)c * Tt * Vv + v] = Gs[c * 65 + vl];
        }
    }
}

extern "C" void kernel_launch(void* const* d_in, const int* in_sizes, int n_in,
                              void* d_out, int out_size)
{
    const float* x      = (const float*)d_in[0];
    const float* gso    = (const float*)d_in[1];
    const float* weight = (const float*)d_in[2];
    const float* bias   = (const float*)d_in[3];
    float* out = (float*)d_out;

    cudaFuncSetAttribute(gconv_kernel,
                         cudaFuncAttributeMaxDynamicSharedMemorySize, SMEM_BYTES);
    gconv_kernel<<<Bb * Tt, TPB, SMEM_BYTES>>>(x, gso, weight, bias, out);
}

// round 3
// speedup vs baseline: 1.2337x; 1.2337x over previous
#include <cuda_runtime.h>

namespace {
constexpr int Bb = 32, Cc = 64, Tt = 64, Vv = 325;
constexpr int TPB = 256;
constexpr int GW  = 48;          // gso staging chunk width (325 = 6*48 + 37)
constexpr int VP  = 128;         // v per pass (3 passes: 0,128,256)

// SMEM layout in floats
constexpr int XS_OFF = 0;                     // Xs[C][V]   = 20800
constexpr int US_OFF = XS_OFF + Cc * Vv;      // Us[V][C]   = 20800
constexpr int W0_OFF = US_OFF + Vv * Cc;      // W0'[C][C]  = 4096
constexpr int W1_OFF = W0_OFF + Cc * Cc;      // W1 [C][C]  = 4096
constexpr int BS_OFF = W1_OFF + Cc * Cc;      // bias       = 64
constexpr int GS_OFF = BS_OFF + Cc;           // Gs[128][GW]= 6144 ; reused as Os[64][65]=4160
constexpr int SMEM_FLOATS = GS_OFF + VP * GW; // 56000
constexpr int SMEM_BYTES  = SMEM_FLOATS * 4;  // 224000 B (~218.8 KiB)
}

__global__ void __launch_bounds__(TPB, 1)
gconv_kernel(const float* __restrict__ x, const float* __restrict__ gso,
             const float* __restrict__ weight, const float* __restrict__ bias,
             float* __restrict__ out)
{
    extern __shared__ float sm[];
    float* Xs  = sm + XS_OFF;   // [C][V]  Xs[i*Vv + v] = x[b,i,t,v]
    float* Us  = sm + US_OFF;   // [V][C]  U = X^T @ W1
    float* W0p = sm + W0_OFF;   // W0 + I (residual folded)
    float* W1s = sm + W1_OFF;
    float* bs  = sm + BS_OFF;
    float* Gs  = sm + GS_OFF;   // [128][GW] gso slab ; reused as Os[64][65]

    const int bt  = blockIdx.x;
    const int b   = bt >> 6;
    const int t   = bt & 63;
    const int tid = threadIdx.x;

    // ---- weights (+ identity fold) ----
    for (int idx = tid; idx < Cc * Cc; idx += TPB) {
        int i = idx >> 6, j = idx & 63;
        W0p[idx] = weight[idx] + (i == j ? 1.0f : 0.0f);
        W1s[idx] = weight[Cc * Cc + idx];
    }
    if (tid < Cc) bs[tid] = bias[tid];

    // ---- load X (coalesced rows of length Vv) ----
    const float* xb = x + ((size_t)(b * Cc) * Tt + t) * Vv;
    for (int idx = tid; idx < Cc * Vv; idx += TPB) {
        int i = idx / Vv, v = idx - i * Vv;
        Xs[idx] = xb[(size_t)i * Tt * Vv + v];
    }
    __syncthreads();

    const int cg = tid & 15;     // 16 c-groups of 4 channels
    const int vq = tid >> 4;     // 16 v-groups of 8 rows -> 128 v per pass
    const int c0 = cg * 4;

    // ================= U[v][c] = sum_i Xs[i][v] * W1[i][c] =================
    for (int vbase = 0; vbase < Vv; vbase += VP) {
        const int v0 = vbase + vq * 8;
        float acc[8][4] = {};
        #pragma unroll 4
        for (int i = 0; i < Cc; i++) {
            float4 wv = *(const float4*)&W1s[i * Cc + c0];
            #pragma unroll
            for (int j = 0; j < 8; j++) {
                float xv = Xs[i * Vv + v0 + j];  // may over-read; stays in smem, store guarded
                acc[j][0] += xv * wv.x; acc[j][1] += xv * wv.y;
                acc[j][2] += xv * wv.z; acc[j][3] += xv * wv.w;
            }
        }
        #pragma unroll
        for (int j = 0; j < 8; j++) {
            int v = v0 + j;
            if (v < Vv)
                *(float4*)&Us[v * Cc + c0] =
                    make_float4(acc[j][0], acc[j][1], acc[j][2], acc[j][3]);
        }
    }
    __syncthreads();

    // ================= out[v][c] = bias + X@W0' + gso @ U =================
    float* ob = out + ((size_t)(b * Cc) * Tt + t) * Vv;

    for (int vbase = 0; vbase < Vv; vbase += VP) {
        const int v0 = vbase + vq * 8;
        float acc[8][4];
        {
            float4 bv = *(const float4*)&bs[c0];
            #pragma unroll
            for (int j = 0; j < 8; j++) {
                acc[j][0] = bv.x; acc[j][1] = bv.y; acc[j][2] = bv.z; acc[j][3] = bv.w;
            }
        }

        // ---- channel mix: + X^T @ W0' ----
        #pragma unroll 4
        for (int i = 0; i < Cc; i++) {
            float4 wv = *(const float4*)&W0p[i * Cc + c0];
            #pragma unroll
            for (int j = 0; j < 8; j++) {
                float xv = Xs[i * Vv + v0 + j];
                acc[j][0] += xv * wv.x; acc[j][1] += xv * wv.y;
                acc[j][2] += xv * wv.z; acc[j][3] += xv * wv.w;
            }
        }

        // ---- graph mix: + gso @ U, staged in [v][q] slabs ----
        for (int wb = 0; wb < Vv; wb += GW) {
            __syncthreads();   // protect Gs/Os reuse
            // stage: Gs[vl][q] = gso[vbase+vl][wb+q]  (coalesced reads, linear writes)
            for (int idx = tid; idx < VP * GW; idx += TPB) {
                int vl = idx / GW, q = idx - vl * GW;
                int v = vbase + vl, k = wb + q;
                Gs[idx] = (v < Vv && k < Vv) ? gso[(size_t)v * Vv + k] : 0.0f;
            }
            __syncthreads();

            const float* gr = &Gs[vq * 8 * GW];
            #pragma unroll 2
            for (int q = 0; q < GW; q += 4) {
                // zero-padded g rows make over-ranged U reads harmless (stay in smem)
                float4 u0 = *(const float4*)&Us[(wb + q + 0) * Cc + c0];
                float4 u1 = *(const float4*)&Us[(wb + q + 1) * Cc + c0];
                float4 u2 = *(const float4*)&Us[(wb + q + 2) * Cc + c0];
                float4 u3 = *(const float4*)&Us[(wb + q + 3) * Cc + c0];
                float4 g[8];
                #pragma unroll
                for (int j = 0; j < 8; j++)
                    g[j] = *(const float4*)&gr[j * GW + q];
                #pragma unroll
                for (int j = 0; j < 8; j++) {
                    acc[j][0] += g[j].x * u0.x; acc[j][1] += g[j].x * u0.y;
                    acc[j][2] += g[j].x * u0.z; acc[j][3] += g[j].x * u0.w;
                    acc[j][0] += g[j].y * u1.x; acc[j][1] += g[j].y * u1.y;
                    acc[j][2] += g[j].y * u1.z; acc[j][3] += g[j].y * u1.w;
                    acc[j][0] += g[j].z * u2.x; acc[j][1] += g[j].z * u2.y;
                    acc[j][2] += g[j].z * u2.z; acc[j][3] += g[j].z * u2.w;
                    acc[j][0] += g[j].w * u3.x; acc[j][1] += g[j].w * u3.y;
                    acc[j][2] += g[j].w * u3.z; acc[j][3] += g[j].w * u3.w;
                }
            }
        }

        // ---- epilogue: transpose via smem (reuse Gs as Os[c][65]), two 64-v halves ----
        #pragma unroll
        for (int h = 0; h < 2; h++) {
            __syncthreads();
            if ((vq >> 3) == h) {
                int vl = (vq & 7) * 8;
                #pragma unroll
                for (int j = 0; j < 8; j++)
                    #pragma unroll
                    for (int k = 0; k < 4; k++)
                        Gs[(c0 + k) * 65 + vl + j] = acc[j][k];
            }
            __syncthreads();
            for (int idx = tid; idx < 64 * 64; idx += TPB) {
                int c = idx >> 6, vl = idx & 63;
                int v = vbase + h * 64 + vl;
                if (v < Vv)
                    ob[(size_t)c * Tt * Vv + v] = Gs[c * 65 + vl];
            }
        }
    }
}

extern "C" void kernel_launch(void* const* d_in, const int* in_sizes, int n_in,
                              void* d_out, int out_size)
{
    const float* x      = (const float*)d_in[0];
    const float* gso    = (const float*)d_in[1];
    const float* weight = (const float*)d_in[2];
    const float* bias   = (const float*)d_in[3];
    float* out = (float*)d_out;

    cudaFuncSetAttribute(gconv_kernel,
                         cudaFuncAttributeMaxDynamicSharedMemorySize, SMEM_BYTES);
    gconv_kernel<<<Bb * Tt, TPB, SMEM_BYTES>>>(x, gso, weight, bias, out);
}

// round 6
// speedup vs baseline: 2.4810x; 2.0111x over previous
#include <cuda_runtime.h>
#include <cuda_bf16.h>
#include <cstdint>

namespace {
constexpr int Cc = 64, Tt = 64, Vv = 325, TPB = 256;
constexpr int BLK   = 36864;     // one 128-v block: X hi[128][72]+lo  (also hosts UT hi/lo)
constexpr int XLO   = 18432;     // lo offset within X block
constexpr int UTLO  = 17408;     // lo offset within UT block ([64][136] bf16 = 17408 B)
constexpr int SM_X  = 0;         // 3 blocks = 110592 B ; reused as Os[64][392] f32 in epilogue
constexpr int SM_W  = 110592;    // W1h,W1l,W0h,W0l each [64][72] bf16 = 9216 B
constexpr int SM_G  = 147456;    // 2 bufs x 36864 (Gh[384][24] + Gl)
constexpr int SM_BIAS = 221184;
constexpr int SM_TOTAL = SM_BIAS + 256;   // 221440 B
}

__device__ __forceinline__ uint32_t smem_u32(const void* p) {
    uint32_t a;
    asm("{ .reg .u64 tmp; cvta.to.shared.u64 tmp, %1; cvt.u32.u64 %0, tmp; }"
        : "=r"(a) : "l"(p));
    return a;
}
__device__ __forceinline__ void bsplit(float a, __nv_bfloat16& h, __nv_bfloat16& l) {
    h = __float2bfloat16(a);
    l = __float2bfloat16(a - __bfloat162float(h));
}

#define LDSM4(r0, r1, r2, r3, addr)                                            \
    asm volatile("ldmatrix.sync.aligned.m8n8.x4.shared.b16 {%0,%1,%2,%3}, [%4];" \
                 : "=r"(r0), "=r"(r1), "=r"(r2), "=r"(r3) : "r"(addr))

#define MMA(d, a0, a1, a2, a3, b0, b1)                                         \
    asm volatile("mma.sync.aligned.m16n8k16.row.col.f32.bf16.bf16.f32 "        \
                 "{%0,%1,%2,%3},{%4,%5,%6,%7},{%8,%9},{%0,%1,%2,%3};"          \
                 : "+f"((d)[0]), "+f"((d)[1]), "+f"((d)[2]), "+f"((d)[3])      \
                 : "r"(a0), "r"(a1), "r"(a2), "r"(a3), "r"(b0), "r"(b1))

__global__ void __launch_bounds__(TPB, 1)
gconv_hmma(const float* __restrict__ x, const float* __restrict__ gso,
           const float* __restrict__ w, const float* __restrict__ bias,
           float* __restrict__ out)
{
    extern __shared__ unsigned char smem[];
    const uint32_t sb = smem_u32(smem);
    const int tid = threadIdx.x, wid = tid >> 5, lid = tid & 31;
    const int bt = blockIdx.x, b = bt >> 6, t = bt & 63;

    // ---- bias -> smem ----
    if (tid < Cc) ((float*)(smem + SM_BIAS))[tid] = bias[tid];

    // ---- weights as B-operands [c][i] row-major (stride 72 bf16), hi/lo ----
    // Reference: out = xp @ W[0] + (gso@xp) @ W[1] + bias + x
    //   => direct path uses weight[0] (+ identity for residual), gso path uses weight[1]
    for (int e = tid; e < Cc * Cc; e += TPB) {
        int i = e >> 6, c = e & 63;
        float w1 = w[Cc * Cc + e];                     // gso path (U = X@W1)
        float w0 = w[e] + (i == c ? 1.0f : 0.0f);      // direct path + residual fold
        uint32_t off = (uint32_t)(c * 144 + i * 2);
        __nv_bfloat16 h, l;
        bsplit(w1, h, l);
        *(__nv_bfloat16*)(smem + SM_W + off)        = h;
        *(__nv_bfloat16*)(smem + SM_W + 9216 + off) = l;
        bsplit(w0, h, l);
        *(__nv_bfloat16*)(smem + SM_W + 18432 + off) = h;
        *(__nv_bfloat16*)(smem + SM_W + 27648 + off) = l;
    }

    // ---- X as A-operand [v][i] row-major (stride 72 bf16), hi/lo, 3 blocks of 128 v ----
    const float* xb = x + ((size_t)(b * Cc) * Tt + t) * Vv;
    #pragma unroll
    for (int ii = 0; ii < 8; ii++) {
        int i = wid * 8 + ii;
        const float* xr = xb + (size_t)i * Tt * Vv;
        for (int v = lid; v < 384; v += 32) {
            float val = (v < Vv) ? xr[v] : 0.0f;
            uint32_t off = (uint32_t)((v >> 7) * BLK + (v & 127) * 144 + i * 2);
            __nv_bfloat16 h, l;
            bsplit(val, h, l);
            *(__nv_bfloat16*)(smem + SM_X + off)       = h;
            *(__nv_bfloat16*)(smem + SM_X + XLO + off) = l;
        }
    }
    __syncthreads();

    // ---- persistent out accumulators (96), init with bias ----
    const float* bsm = (const float*)(smem + SM_BIAS);
    float oacc[3][8][4];
    #pragma unroll
    for (int mt = 0; mt < 3; mt++)
        #pragma unroll
        for (int nt = 0; nt < 8; nt++)
            #pragma unroll
            for (int r = 0; r < 4; r++)
                oacc[mt][nt][r] = bsm[nt * 8 + (lid & 3) * 2 + (r & 1)];

    // ================= phase 1: U = X@W1 ; oacc = bias + X@W0' =================
    // then per-block re-split U -> UT[c][v'] overlaying the dead X block
    #pragma unroll
    for (int mt = 0; mt < 3; mt++) {
        float uacc[8][4] = {};
        const uint32_t xa = sb + SM_X + mt * BLK +
                            (wid * 16 + (lid & 15)) * 144 + (lid >> 4) * 16;
        #pragma unroll
        for (int k = 0; k < 4; k++) {
            uint32_t aH0, aH1, aH2, aH3, aL0, aL1, aL2, aL3;
            LDSM4(aH0, aH1, aH2, aH3, xa + k * 32);
            LDSM4(aL0, aL1, aL2, aL3, xa + XLO + k * 32);
            #pragma unroll
            for (int np = 0; np < 4; np++) {
                const uint32_t wa = sb + SM_W +
                    (np * 16 + (lid & 15)) * 144 + (lid >> 4) * 16 + k * 32;
                uint32_t h0, h1, h2, h3, l0, l1, l2, l3;
                // W1 (U accumulation)
                LDSM4(h0, h1, h2, h3, wa);
                LDSM4(l0, l1, l2, l3, wa + 9216);
                MMA(uacc[np * 2],     aH0, aH1, aH2, aH3, h0, h2);
                MMA(uacc[np * 2],     aH0, aH1, aH2, aH3, l0, l2);
                MMA(uacc[np * 2],     aL0, aL1, aL2, aL3, h0, h2);
                MMA(uacc[np * 2 + 1], aH0, aH1, aH2, aH3, h1, h3);
                MMA(uacc[np * 2 + 1], aH0, aH1, aH2, aH3, l1, l3);
                MMA(uacc[np * 2 + 1], aL0, aL1, aL2, aL3, h1, h3);
                // W0' (out accumulation)
                LDSM4(h0, h1, h2, h3, wa + 18432);
                LDSM4(l0, l1, l2, l3, wa + 27648);
                MMA(oacc[mt][np * 2],     aH0, aH1, aH2, aH3, h0, h2);
                MMA(oacc[mt][np * 2],     aH0, aH1, aH2, aH3, l0, l2);
                MMA(oacc[mt][np * 2],     aL0, aL1, aL2, aL3, h0, h2);
                MMA(oacc[mt][np * 2 + 1], aH0, aH1, aH2, aH3, h1, h3);
                MMA(oacc[mt][np * 2 + 1], aH0, aH1, aH2, aH3, l1, l3);
                MMA(oacc[mt][np * 2 + 1], aL0, aL1, aL2, aL3, h1, h3);
            }
        }
        __syncthreads();   // all warps done reading X block mt
        // write UT block mt: UT[c][k'] (stride 136 bf16), k' = v within block
        #pragma unroll
        for (int nt = 0; nt < 8; nt++)
            #pragma unroll
            for (int r = 0; r < 4; r++) {
                int c  = nt * 8 + (lid & 3) * 2 + (r & 1);
                int kp = wid * 16 + (lid >> 2) + ((r >> 1) << 3);
                uint32_t off = (uint32_t)(mt * BLK + c * 272 + kp * 2);
                __nv_bfloat16 h, l;
                bsplit(uacc[nt][r], h, l);
                *(__nv_bfloat16*)(smem + SM_X + off)        = h;
                *(__nv_bfloat16*)(smem + SM_X + UTLO + off) = l;
            }
        __syncthreads();
    }

    // ================= phase 2: oacc += G @ U, 21 k16-chunks =================
    float gr[24];
    {   // prefetch chunk 0
        #pragma unroll
        for (int j = 0; j < 24; j++) {
            int e = tid + j * 256, row = e >> 4, col = e & 15;
            gr[j] = (row < Vv && col < Vv) ? gso[(size_t)row * Vv + col] : 0.0f;
        }
    }
    for (int kk = 0; kk < 21; kk++) {
        __syncthreads();   // buf[kk&1]'s previous consumer (chunk kk-2) is done
        const int gbuf = SM_G + (kk & 1) * BLK;
        #pragma unroll
        for (int j = 0; j < 24; j++) {
            int e = tid + j * 256, row = e >> 4, col = e & 15;
            uint32_t off = (uint32_t)(row * 48 + col * 2);
            __nv_bfloat16 h, l;
            bsplit(gr[j], h, l);
            *(__nv_bfloat16*)(smem + gbuf + off)         = h;
            *(__nv_bfloat16*)(smem + gbuf + 18432 + off) = l;
        }
        if (kk < 20) {   // prefetch next chunk (overlaps with this chunk's MMAs)
            int kn = kk + 1;
            #pragma unroll
            for (int j = 0; j < 24; j++) {
                int e = tid + j * 256, row = e >> 4, kg = kn * 16 + (e & 15);
                gr[j] = (row < Vv && kg < Vv) ? gso[(size_t)row * Vv + kg] : 0.0f;
            }
        }
        __syncthreads();

        const uint32_t gb = sb + gbuf;
        const uint32_t ub = sb + SM_X + (kk >> 3) * BLK + (kk & 7) * 32;
        #pragma unroll
        for (int mt = 0; mt < 3; mt++) {
            const uint32_t ga = gb + (mt * 128 + wid * 16 + (lid & 15)) * 48 +
                                (lid >> 4) * 16;
            uint32_t aH0, aH1, aH2, aH3, aL0, aL1, aL2, aL3;
            LDSM4(aH0, aH1, aH2, aH3, ga);
            LDSM4(aL0, aL1, aL2, aL3, ga + 18432);
            #pragma unroll
            for (int np = 0; np < 4; np++) {
                const uint32_t ua = ub + (np * 16 + (lid & 15)) * 272 +
                                    (lid >> 4) * 16;
                uint32_t h0, h1, h2, h3, l0, l1, l2, l3;
                LDSM4(h0, h1, h2, h3, ua);
                LDSM4(l0, l1, l2, l3, ua + UTLO);
                MMA(oacc[mt][np * 2],     aH0, aH1, aH2, aH3, h0, h2);
                MMA(oacc[mt][np * 2],     aH0, aH1, aH2, aH3, l0, l2);
                MMA(oacc[mt][np * 2],     aL0, aL1, aL2, aL3, h0, h2);
                MMA(oacc[mt][np * 2 + 1], aH0, aH1, aH2, aH3, h1, h3);
                MMA(oacc[mt][np * 2 + 1], aH0, aH1, aH2, aH3, l1, l3);
                MMA(oacc[mt][np * 2 + 1], aL0, aL1, aL2, aL3, h1, h3);
            }
        }
    }
    __syncthreads();

    // ================= epilogue: transpose via smem, coalesced [c][v] stores =========
    float* Os = (float*)(smem + SM_X);   // [64][392] f32, UT dead
    #pragma unroll
    for (int mt = 0; mt < 3; mt++)
        #pragma unroll
        for (int nt = 0; nt < 8; nt++)
            #pragma unroll
            for (int r = 0; r < 4; r++) {
                int c = nt * 8 + (lid & 3) * 2 + (r & 1);
                int v = mt * 128 + wid * 16 + (lid >> 2) + ((r >> 1) << 3);
                Os[c * 392 + v] = oacc[mt][nt][r];
            }
    __syncthreads();
    float* ob = out + ((size_t)(b * Cc) * Tt + t) * Vv;
    #pragma unroll
    for (int cc = 0; cc < 8; cc++) {
        int c = wid * 8 + cc;
        float* orow = ob + (size_t)c * Tt * Vv;
        for (int v = lid; v < Vv; v += 32)
            orow[v] = Os[c * 392 + v];
    }
}

extern "C" void kernel_launch(void* const* d_in, const int* in_sizes, int n_in,
                              void* d_out, int out_size)
{
    const float* x      = (const float*)d_in[0];
    const float* gso    = (const float*)d_in[1];
    const float* weight = (const float*)d_in[2];
    const float* bias   = (const float*)d_in[3];
    float* out = (float*)d_out;

    cudaFuncSetAttribute(gconv_hmma,
                         cudaFuncAttributeMaxDynamicSharedMemorySize, SM_TOTAL);
    gconv_hmma<<<32 * 64, TPB, SM_TOTAL>>>(x, gso, weight, bias, out);
}

// round 7
// speedup vs baseline: 3.0499x; 1.2293x over previous
#include <cuda_runtime.h>
#include <cuda_bf16.h>
#include <cstdint>

namespace {
constexpr int Cc = 64, Tt = 64, Vv = 325, TPB = 256;
constexpr int NCHUNK = 21;       // k16 chunks covering 325 (21*16 = 336, padded)
constexpr int BLK   = 36864;     // one 128-v block: X hi[128][72]+lo  (also hosts UT hi/lo)
constexpr int XLO   = 18432;     // lo offset within X block
constexpr int UTLO  = 17408;     // lo offset within UT block ([64][136] bf16 = 17408 B)
constexpr int SM_X  = 0;         // 3 blocks = 110592 B ; reused as Os[64][392] f32 in epilogue
constexpr int SM_W  = 110592;    // W1h,W1l,W0h,W0l each [64][72] bf16 = 9216 B
constexpr int SM_G  = 147456;    // 2 bufs x 36864 (Gh[384][24] + Gl), cp.async targets
constexpr int SM_BIAS = 221184;
constexpr int SM_TOTAL = SM_BIAS + 256;   // 221440 B
}

// Pre-converted gso: per chunk the exact smem image [hi: 384x48B][lo: 384x48B]
__device__ __align__(16) unsigned char g_gso_bf16[NCHUNK * BLK];   // 774 KB

__device__ __forceinline__ uint32_t smem_u32(const void* p) {
    uint32_t a;
    asm("{ .reg .u64 tmp; cvta.to.shared.u64 tmp, %1; cvt.u32.u64 %0, tmp; }"
        : "=r"(a) : "l"(p));
    return a;
}
__device__ __forceinline__ void bsplit(float a, __nv_bfloat16& h, __nv_bfloat16& l) {
    h = __float2bfloat16(a);
    l = __float2bfloat16(a - __bfloat162float(h));
}
__device__ __forceinline__ void cpasync16(uint32_t dst, const void* src) {
    asm volatile("cp.async.cg.shared.global [%0], [%1], 16;"
                 :: "r"(dst), "l"(src) : "memory");
}

#define LDSM4(r0, r1, r2, r3, addr)                                            \
    asm volatile("ldmatrix.sync.aligned.m8n8.x4.shared.b16 {%0,%1,%2,%3}, [%4];" \
                 : "=r"(r0), "=r"(r1), "=r"(r2), "=r"(r3) : "r"(addr))

#define MMA(d, a0, a1, a2, a3, b0, b1)                                         \
    asm volatile("mma.sync.aligned.m16n8k16.row.col.f32.bf16.bf16.f32 "        \
                 "{%0,%1,%2,%3},{%4,%5,%6,%7},{%8,%9},{%0,%1,%2,%3};"          \
                 : "+f"((d)[0]), "+f"((d)[1]), "+f"((d)[2]), "+f"((d)[3])      \
                 : "r"(a0), "r"(a1), "r"(a2), "r"(a3), "r"(b0), "r"(b1))

// ---------------- prepass: gso f32 -> bf16 hi/lo chunk images ----------------
__global__ void prep_gso(const float* __restrict__ gso)
{
    int idx = blockIdx.x * blockDim.x + threadIdx.x;     // NCHUNK*384*24
    if (idx >= NCHUNK * 384 * 24) return;
    int kk = idx / (384 * 24);
    int r  = (idx / 24) % 384;
    int c  = idx % 24;
    int kg = kk * 16 + c;
    float val = (c < 16 && r < Vv && kg < Vv) ? gso[(size_t)r * Vv + kg] : 0.0f;
    __nv_bfloat16 h, l;
    bsplit(val, h, l);
    unsigned char* base = g_gso_bf16 + (size_t)kk * BLK;
    *(__nv_bfloat16*)(base + r * 48 + c * 2)         = h;
    *(__nv_bfloat16*)(base + 18432 + r * 48 + c * 2) = l;
}

// ---------------- main kernel ----------------
__global__ void __launch_bounds__(TPB, 1)
gconv_hmma(const float* __restrict__ x, const float* __restrict__ gso,
           const float* __restrict__ w, const float* __restrict__ bias,
           float* __restrict__ out)
{
    extern __shared__ unsigned char smem[];
    const uint32_t sb = smem_u32(smem);
    const int tid = threadIdx.x, wid = tid >> 5, lid = tid & 31;
    const int bt = blockIdx.x, b = bt >> 6, t = bt & 63;

    // ---- kick off chunk-0 gso copy immediately (overlaps X staging + phase 1) ----
    {
        const unsigned char* src = g_gso_bf16;
        uint32_t dst = sb + SM_G;
        #pragma unroll
        for (int j = 0; j < 9; j++)
            cpasync16(dst + tid * 16 + j * 4096, src + tid * 16 + j * 4096);
        asm volatile("cp.async.commit_group;" ::: "memory");
    }

    // ---- bias -> smem ----
    if (tid < Cc) ((float*)(smem + SM_BIAS))[tid] = bias[tid];

    // ---- weights as B-operands [c][i] row-major (stride 72 bf16), hi/lo ----
    // out = xp @ W[0] + (gso@xp) @ W[1] + bias + x
    for (int e = tid; e < Cc * Cc; e += TPB) {
        int i = e >> 6, c = e & 63;
        float w1 = w[Cc * Cc + e];                     // gso path (U = X@W1)
        float w0 = w[e] + (i == c ? 1.0f : 0.0f);      // direct path + residual fold
        uint32_t off = (uint32_t)(c * 144 + i * 2);
        __nv_bfloat16 h, l;
        bsplit(w1, h, l);
        *(__nv_bfloat16*)(smem + SM_W + off)        = h;
        *(__nv_bfloat16*)(smem + SM_W + 9216 + off) = l;
        bsplit(w0, h, l);
        *(__nv_bfloat16*)(smem + SM_W + 18432 + off) = h;
        *(__nv_bfloat16*)(smem + SM_W + 27648 + off) = l;
    }

    // ---- X as A-operand [v][i] row-major (stride 72 bf16), hi/lo ----
    const float* xb = x + ((size_t)(b * Cc) * Tt + t) * Vv;
    #pragma unroll
    for (int ii = 0; ii < 8; ii++) {
        int i = wid * 8 + ii;
        const float* xr = xb + (size_t)i * Tt * Vv;
        for (int v = lid; v < 384; v += 32) {
            float val = (v < Vv) ? xr[v] : 0.0f;
            uint32_t off = (uint32_t)((v >> 7) * BLK + (v & 127) * 144 + i * 2);
            __nv_bfloat16 h, l;
            bsplit(val, h, l);
            *(__nv_bfloat16*)(smem + SM_X + off)       = h;
            *(__nv_bfloat16*)(smem + SM_X + XLO + off) = l;
        }
    }
    __syncthreads();

    // ---- persistent out accumulators, init with bias ----
    const float* bsm = (const float*)(smem + SM_BIAS);
    float oacc[3][8][4];
    #pragma unroll
    for (int mt = 0; mt < 3; mt++)
        #pragma unroll
        for (int nt = 0; nt < 8; nt++)
            #pragma unroll
            for (int r = 0; r < 4; r++)
                oacc[mt][nt][r] = bsm[nt * 8 + (lid & 3) * 2 + (r & 1)];

    // ================= phase 1: U = X@W1 ; oacc = bias + X@W0' =================
    #pragma unroll
    for (int mt = 0; mt < 3; mt++) {
        float uacc[8][4] = {};
        const uint32_t xa = sb + SM_X + mt * BLK +
                            (wid * 16 + (lid & 15)) * 144 + (lid >> 4) * 16;
        #pragma unroll
        for (int k = 0; k < 4; k++) {
            uint32_t aH0, aH1, aH2, aH3, aL0, aL1, aL2, aL3;
            LDSM4(aH0, aH1, aH2, aH3, xa + k * 32);
            LDSM4(aL0, aL1, aL2, aL3, xa + XLO + k * 32);
            #pragma unroll
            for (int np = 0; np < 4; np++) {
                const uint32_t wa = sb + SM_W +
                    (np * 16 + (lid & 15)) * 144 + (lid >> 4) * 16 + k * 32;
                uint32_t h0, h1, h2, h3, l0, l1, l2, l3;
                LDSM4(h0, h1, h2, h3, wa);
                LDSM4(l0, l1, l2, l3, wa + 9216);
                MMA(uacc[np * 2],     aH0, aH1, aH2, aH3, h0, h2);
                MMA(uacc[np * 2],     aH0, aH1, aH2, aH3, l0, l2);
                MMA(uacc[np * 2],     aL0, aL1, aL2, aL3, h0, h2);
                MMA(uacc[np * 2 + 1], aH0, aH1, aH2, aH3, h1, h3);
                MMA(uacc[np * 2 + 1], aH0, aH1, aH2, aH3, l1, l3);
                MMA(uacc[np * 2 + 1], aL0, aL1, aL2, aL3, h1, h3);
                LDSM4(h0, h1, h2, h3, wa + 18432);
                LDSM4(l0, l1, l2, l3, wa + 27648);
                MMA(oacc[mt][np * 2],     aH0, aH1, aH2, aH3, h0, h2);
                MMA(oacc[mt][np * 2],     aH0, aH1, aH2, aH3, l0, l2);
                MMA(oacc[mt][np * 2],     aL0, aL1, aL2, aL3, h0, h2);
                MMA(oacc[mt][np * 2 + 1], aH0, aH1, aH2, aH3, h1, h3);
                MMA(oacc[mt][np * 2 + 1], aH0, aH1, aH2, aH3, l1, l3);
                MMA(oacc[mt][np * 2 + 1], aL0, aL1, aL2, aL3, h1, h3);
            }
        }
        __syncthreads();   // all warps done reading X block mt
        #pragma unroll
        for (int nt = 0; nt < 8; nt++)
            #pragma unroll
            for (int r = 0; r < 4; r++) {
                int c  = nt * 8 + (lid & 3) * 2 + (r & 1);
                int kp = wid * 16 + (lid >> 2) + ((r >> 1) << 3);
                uint32_t off = (uint32_t)(mt * BLK + c * 272 + kp * 2);
                __nv_bfloat16 h, l;
                bsplit(uacc[nt][r], h, l);
                *(__nv_bfloat16*)(smem + SM_X + off)        = h;
                *(__nv_bfloat16*)(smem + SM_X + UTLO + off) = l;
            }
        __syncthreads();
    }

    // wait for chunk-0 gso copy (long since landed, but make it explicit)
    asm volatile("cp.async.wait_group 0;" ::: "memory");
    __syncthreads();

    // ================= phase 2: oacc += G @ U, cp.async pipelined =================
    for (int kk = 0; kk < NCHUNK; kk++) {
        if (kk < NCHUNK - 1) {   // issue next chunk's copy before this chunk's MMAs
            const unsigned char* src = g_gso_bf16 + (size_t)(kk + 1) * BLK;
            uint32_t dst = sb + SM_G + ((kk + 1) & 1) * BLK;
            #pragma unroll
            for (int j = 0; j < 9; j++)
                cpasync16(dst + tid * 16 + j * 4096, src + tid * 16 + j * 4096);
            asm volatile("cp.async.commit_group;" ::: "memory");
        }

        const uint32_t gb = sb + SM_G + (kk & 1) * BLK;
        const uint32_t ub = sb + SM_X + (kk >> 3) * BLK + (kk & 7) * 32;
        #pragma unroll
        for (int mt = 0; mt < 3; mt++) {
            const uint32_t ga = gb + (mt * 128 + wid * 16 + (lid & 15)) * 48 +
                                (lid >> 4) * 16;
            uint32_t aH0, aH1, aH2, aH3, aL0, aL1, aL2, aL3;
            LDSM4(aH0, aH1, aH2, aH3, ga);
            LDSM4(aL0, aL1, aL2, aL3, ga + 18432);
            #pragma unroll
            for (int np = 0; np < 4; np++) {
                const uint32_t ua = ub + (np * 16 + (lid & 15)) * 272 +
                                    (lid >> 4) * 16;
                uint32_t h0, h1, h2, h3, l0, l1, l2, l3;
                LDSM4(h0, h1, h2, h3, ua);
                LDSM4(l0, l1, l2, l3, ua + UTLO);
                MMA(oacc[mt][np * 2],     aH0, aH1, aH2, aH3, h0, h2);
                MMA(oacc[mt][np * 2],     aH0, aH1, aH2, aH3, l0, l2);
                MMA(oacc[mt][np * 2],     aL0, aL1, aL2, aL3, h0, h2);
                MMA(oacc[mt][np * 2 + 1], aH0, aH1, aH2, aH3, h1, h3);
                MMA(oacc[mt][np * 2 + 1], aH0, aH1, aH2, aH3, l1, l3);
                MMA(oacc[mt][np * 2 + 1], aL0, aL1, aL2, aL3, h1, h3);
            }
        }

        if (kk < NCHUNK - 1) {
            asm volatile("cp.async.wait_group 0;" ::: "memory");
            __syncthreads();
        }
    }
    __syncthreads();

    // ================= epilogue: transpose via smem, coalesced [c][v] stores =========
    float* Os = (float*)(smem + SM_X);   // [64][392] f32, UT dead
    #pragma unroll
    for (int mt = 0; mt < 3; mt++)
        #pragma unroll
        for (int nt = 0; nt < 8; nt++)
            #pragma unroll
            for (int r = 0; r < 4; r++) {
                int c = nt * 8 + (lid & 3) * 2 + (r & 1);
                int v = mt * 128 + wid * 16 + (lid >> 2) + ((r >> 1) << 3);
                Os[c * 392 + v] = oacc[mt][nt][r];
            }
    __syncthreads();
    float* ob = out + ((size_t)(b * Cc) * Tt + t) * Vv;
    #pragma unroll
    for (int cc = 0; cc < 8; cc++) {
        int c = wid * 8 + cc;
        float* orow = ob + (size_t)c * Tt * Vv;
        for (int v = lid; v < Vv; v += 32)
            orow[v] = Os[c * 392 + v];
    }
}

extern "C" void kernel_launch(void* const* d_in, const int* in_sizes, int n_in,
                              void* d_out, int out_size)
{
    const float* x      = (const float*)d_in[0];
    const float* gso    = (const float*)d_in[1];
    const float* weight = (const float*)d_in[2];
    const float* bias   = (const float*)d_in[3];
    float* out = (float*)d_out;

    prep_gso<<<(NCHUNK * 384 * 24 + TPB - 1) / TPB, TPB>>>(gso);

    cudaFuncSetAttribute(gconv_hmma,
                         cudaFuncAttributeMaxDynamicSharedMemorySize, SM_TOTAL);
    gconv_hmma<<<32 * 64, TPB, SM_TOTAL>>>(x, gso, weight, bias, out);
}

// round 8
// speedup vs baseline: 3.4209x; 1.1217x over previous
#include <cuda_runtime.h>
#include <cuda_bf16.h>
#include <cstdint>

namespace {
constexpr int Cc = 64, Tt = 64, Vv = 325, TPB = 384;
constexpr int NCHUNK = 21;       // k16 chunks covering 325 (21*16 = 336, padded)
constexpr int BLK   = 36864;     // one 128-v block: X hi[128][72]+lo  (also hosts UT hi/lo)
constexpr int XLO   = 18432;     // lo offset within X block
constexpr int UTLO  = 17408;     // lo offset within UT block ([64][136] bf16 = 17408 B)
constexpr int SM_X  = 0;         // 3 blocks = 110592 B ; reused as Os[64][396] f32 in epilogue
constexpr int SM_W  = 110592;    // W1h,W1l,W0h,W0l each [64][72] bf16 = 9216 B
constexpr int SM_G  = 147456;    // 2 bufs x 36864 (Gh[384][24] + Gl), cp.async targets
constexpr int SM_BIAS = 221184;
constexpr int SM_TOTAL = SM_BIAS + 256;   // 221440 B
}

// Pre-converted gso: per chunk the exact smem image [hi: 384x48B][lo: 384x48B]
__device__ __align__(16) unsigned char g_gso_bf16[NCHUNK * BLK];   // 774 KB

__device__ __forceinline__ uint32_t smem_u32(const void* p) {
    uint32_t a;
    asm("{ .reg .u64 tmp; cvta.to.shared.u64 tmp, %1; cvt.u32.u64 %0, tmp; }"
        : "=r"(a) : "l"(p));
    return a;
}
__device__ __forceinline__ void bsplit(float a, __nv_bfloat16& h, __nv_bfloat16& l) {
    h = __float2bfloat16(a);
    l = __float2bfloat16(a - __bfloat162float(h));
}
__device__ __forceinline__ void cpasync16(uint32_t dst, const void* src) {
    asm volatile("cp.async.cg.shared.global [%0], [%1], 16;"
                 :: "r"(dst), "l"(src) : "memory");
}

#define LDSM4(r0, r1, r2, r3, addr)                                            \
    asm volatile("ldmatrix.sync.aligned.m8n8.x4.shared.b16 {%0,%1,%2,%3}, [%4];" \
                 : "=r"(r0), "=r"(r1), "=r"(r2), "=r"(r3) : "r"(addr))

#define MMA(d, a0, a1, a2, a3, b0, b1)                                         \
    asm volatile("mma.sync.aligned.m16n8k16.row.col.f32.bf16.bf16.f32 "        \
                 "{%0,%1,%2,%3},{%4,%5,%6,%7},{%8,%9},{%0,%1,%2,%3};"          \
                 : "+f"((d)[0]), "+f"((d)[1]), "+f"((d)[2]), "+f"((d)[3])      \
                 : "r"(a0), "r"(a1), "r"(a2), "r"(a3), "r"(b0), "r"(b1))

// ---------------- prepass: gso f32 -> bf16 hi/lo chunk images ----------------
__global__ void prep_gso(const float* __restrict__ gso)
{
    int idx = blockIdx.x * blockDim.x + threadIdx.x;     // NCHUNK*384*24
    if (idx >= NCHUNK * 384 * 24) return;
    int kk = idx / (384 * 24);
    int r  = (idx / 24) % 384;
    int c  = idx % 24;
    int kg = kk * 16 + c;
    float val = (c < 16 && r < Vv && kg < Vv) ? gso[(size_t)r * Vv + kg] : 0.0f;
    __nv_bfloat16 h, l;
    bsplit(val, h, l);
    unsigned char* base = g_gso_bf16 + (size_t)kk * BLK;
    *(__nv_bfloat16*)(base + r * 48 + c * 2)         = h;
    *(__nv_bfloat16*)(base + 18432 + r * 48 + c * 2) = l;
}

// ---------------- main kernel: 12 warps, 32 M-rows per warp ----------------
__global__ void __launch_bounds__(TPB, 1)
gconv_hmma(const float* __restrict__ x, const float* __restrict__ gso,
           const float* __restrict__ w, const float* __restrict__ bias,
           float* __restrict__ out)
{
    extern __shared__ unsigned char smem[];
    const uint32_t sb = smem_u32(smem);
    const int tid = threadIdx.x, wid = tid >> 5, lid = tid & 31;
    const int bt = blockIdx.x, b = bt >> 6, t = bt & 63;

    // ---- kick off chunk-0 gso copy immediately (overlaps X staging + phase 1) ----
    {
        const unsigned char* src = g_gso_bf16;
        uint32_t dst = sb + SM_G;
        #pragma unroll
        for (int j = 0; j < 6; j++)
            cpasync16(dst + tid * 16 + j * 6144, src + tid * 16 + j * 6144);
        asm volatile("cp.async.commit_group;" ::: "memory");
    }

    // ---- bias -> smem ----
    if (tid < Cc) ((float*)(smem + SM_BIAS))[tid] = bias[tid];

    // ---- weights as B-operands [c][i] row-major (stride 72 bf16), hi/lo ----
    // out = xp @ W[0] + (gso@xp) @ W[1] + bias + x
    for (int e = tid; e < Cc * Cc; e += TPB) {
        int i = e >> 6, c = e & 63;
        float w1 = w[Cc * Cc + e];                     // gso path (U = X@W1)
        float w0 = w[e] + (i == c ? 1.0f : 0.0f);      // direct path + residual fold
        uint32_t off = (uint32_t)(c * 144 + i * 2);
        __nv_bfloat16 h, l;
        bsplit(w1, h, l);
        *(__nv_bfloat16*)(smem + SM_W + off)        = h;
        *(__nv_bfloat16*)(smem + SM_W + 9216 + off) = l;
        bsplit(w0, h, l);
        *(__nv_bfloat16*)(smem + SM_W + 18432 + off) = h;
        *(__nv_bfloat16*)(smem + SM_W + 27648 + off) = l;
    }

    // ---- X as A-operand [v][i] row-major (stride 72 bf16), hi/lo ----
    const float* xb = x + ((size_t)(b * Cc) * Tt + t) * Vv;
    #pragma unroll
    for (int ii = 0; ii < 6; ii++) {
        int i = wid + 12 * ii;
        if (i < Cc) {
            const float* xr = xb + (size_t)i * Tt * Vv;
            for (int v = lid; v < 384; v += 32) {
                float val = (v < Vv) ? xr[v] : 0.0f;
                uint32_t off = (uint32_t)((v >> 7) * BLK + (v & 127) * 144 + i * 2);
                __nv_bfloat16 h, l;
                bsplit(val, h, l);
                *(__nv_bfloat16*)(smem + SM_X + off)       = h;
                *(__nv_bfloat16*)(smem + SM_X + XLO + off) = l;
            }
        }
    }
    __syncthreads();

    // ---- persistent out accumulators (2 m16 subtiles/warp), init with bias ----
    const float* bsm = (const float*)(smem + SM_BIAS);
    float oacc[2][8][4];
    #pragma unroll
    for (int s = 0; s < 2; s++)
        #pragma unroll
        for (int nt = 0; nt < 8; nt++)
            #pragma unroll
            for (int r = 0; r < 4; r++)
                oacc[s][nt][r] = bsm[nt * 8 + (lid & 3) * 2 + (r & 1)];

    // ================= phase 1: U = X@W1 ; oacc = bias + X@W0' (single pass) =========
    // warp owns M-rows [wid*32, wid*32+32): block wid>>2, in-block row (wid&3)*32
    float uacc[2][8][4] = {};
    {
        const uint32_t xa0 = sb + SM_X + (wid >> 2) * BLK +
                             ((wid & 3) * 32 + (lid & 15)) * 144 + (lid >> 4) * 16;
        #pragma unroll
        for (int k = 0; k < 4; k++) {
            uint32_t a[2][8];
            #pragma unroll
            for (int s = 0; s < 2; s++) {
                LDSM4(a[s][0], a[s][1], a[s][2], a[s][3], xa0 + s * 2304 + k * 32);
                LDSM4(a[s][4], a[s][5], a[s][6], a[s][7], xa0 + s * 2304 + XLO + k * 32);
            }
            #pragma unroll
            for (int np = 0; np < 4; np++) {
                const uint32_t wa = sb + SM_W +
                    (np * 16 + (lid & 15)) * 144 + (lid >> 4) * 16 + k * 32;
                uint32_t h0, h1, h2, h3, l0, l1, l2, l3;
                LDSM4(h0, h1, h2, h3, wa);
                LDSM4(l0, l1, l2, l3, wa + 9216);
                #pragma unroll
                for (int s = 0; s < 2; s++) {
                    MMA(uacc[s][np * 2],     a[s][0], a[s][1], a[s][2], a[s][3], h0, h2);
                    MMA(uacc[s][np * 2],     a[s][0], a[s][1], a[s][2], a[s][3], l0, l2);
                    MMA(uacc[s][np * 2],     a[s][4], a[s][5], a[s][6], a[s][7], h0, h2);
                    MMA(uacc[s][np * 2 + 1], a[s][0], a[s][1], a[s][2], a[s][3], h1, h3);
                    MMA(uacc[s][np * 2 + 1], a[s][0], a[s][1], a[s][2], a[s][3], l1, l3);
                    MMA(uacc[s][np * 2 + 1], a[s][4], a[s][5], a[s][6], a[s][7], h1, h3);
                }
                LDSM4(h0, h1, h2, h3, wa + 18432);
                LDSM4(l0, l1, l2, l3, wa + 27648);
                #pragma unroll
                for (int s = 0; s < 2; s++) {
                    MMA(oacc[s][np * 2],     a[s][0], a[s][1], a[s][2], a[s][3], h0, h2);
                    MMA(oacc[s][np * 2],     a[s][0], a[s][1], a[s][2], a[s][3], l0, l2);
                    MMA(oacc[s][np * 2],     a[s][4], a[s][5], a[s][6], a[s][7], h0, h2);
                    MMA(oacc[s][np * 2 + 1], a[s][0], a[s][1], a[s][2], a[s][3], h1, h3);
                    MMA(oacc[s][np * 2 + 1], a[s][0], a[s][1], a[s][2], a[s][3], l1, l3);
                    MMA(oacc[s][np * 2 + 1], a[s][4], a[s][5], a[s][6], a[s][7], h1, h3);
                }
            }
        }
    }
    __syncthreads();   // all warps done reading X
    // write UT: [c][k'] stride 272B per 128-block; kp stays in warp's own block
    #pragma unroll
    for (int s = 0; s < 2; s++)
        #pragma unroll
        for (int nt = 0; nt < 8; nt++)
            #pragma unroll
            for (int r = 0; r < 4; r++) {
                int c  = nt * 8 + (lid & 3) * 2 + (r & 1);
                int kp = wid * 32 + s * 16 + (lid >> 2) + ((r >> 1) << 3);
                uint32_t off = (uint32_t)((kp >> 7) * BLK + c * 272 + (kp & 127) * 2);
                __nv_bfloat16 h, l;
                bsplit(uacc[s][nt][r], h, l);
                *(__nv_bfloat16*)(smem + SM_X + off)        = h;
                *(__nv_bfloat16*)(smem + SM_X + UTLO + off) = l;
            }

    // wait for chunk-0 gso copy, make UT + G visible
    asm volatile("cp.async.wait_group 0;" ::: "memory");
    __syncthreads();

    // ================= phase 2: oacc += G @ U, cp.async pipelined =================
    for (int kk = 0; kk < NCHUNK; kk++) {
        if (kk < NCHUNK - 1) {   // issue next chunk's copy before this chunk's MMAs
            const unsigned char* src = g_gso_bf16 + (size_t)(kk + 1) * BLK;
            uint32_t dst = sb + SM_G + ((kk + 1) & 1) * BLK;
            #pragma unroll
            for (int j = 0; j < 6; j++)
                cpasync16(dst + tid * 16 + j * 6144, src + tid * 16 + j * 6144);
            asm volatile("cp.async.commit_group;" ::: "memory");
        }

        const uint32_t gb = sb + SM_G + (kk & 1) * BLK;
        const uint32_t ub = sb + SM_X + (kk >> 3) * BLK + (kk & 7) * 32;

        // load U B-fragments once, reuse for both m-subtiles
        uint32_t uf[4][8];
        #pragma unroll
        for (int np = 0; np < 4; np++) {
            const uint32_t ua = ub + (np * 16 + (lid & 15)) * 272 + (lid >> 4) * 16;
            LDSM4(uf[np][0], uf[np][1], uf[np][2], uf[np][3], ua);
            LDSM4(uf[np][4], uf[np][5], uf[np][6], uf[np][7], ua + UTLO);
        }
        #pragma unroll
        for (int s = 0; s < 2; s++) {
            const uint32_t ga = gb + (wid * 32 + s * 16 + (lid & 15)) * 48 +
                                (lid >> 4) * 16;
            uint32_t aH0, aH1, aH2, aH3, aL0, aL1, aL2, aL3;
            LDSM4(aH0, aH1, aH2, aH3, ga);
            LDSM4(aL0, aL1, aL2, aL3, ga + 18432);
            #pragma unroll
            for (int np = 0; np < 4; np++) {
                MMA(oacc[s][np * 2],     aH0, aH1, aH2, aH3, uf[np][0], uf[np][2]);
                MMA(oacc[s][np * 2],     aH0, aH1, aH2, aH3, uf[np][4], uf[np][6]);
                MMA(oacc[s][np * 2],     aL0, aL1, aL2, aL3, uf[np][0], uf[np][2]);
                MMA(oacc[s][np * 2 + 1], aH0, aH1, aH2, aH3, uf[np][1], uf[np][3]);
                MMA(oacc[s][np * 2 + 1], aH0, aH1, aH2, aH3, uf[np][5], uf[np][7]);
                MMA(oacc[s][np * 2 + 1], aL0, aL1, aL2, aL3, uf[np][1], uf[np][3]);
            }
        }

        if (kk < NCHUNK - 1) {
            asm volatile("cp.async.wait_group 0;" ::: "memory");
            __syncthreads();
        }
    }
    __syncthreads();

    // ================= epilogue: transpose via smem, coalesced [c][v] stores =========
    float* Os = (float*)(smem + SM_X);   // [64][396] f32, UT dead
    #pragma unroll
    for (int s = 0; s < 2; s++)
        #pragma unroll
        for (int nt = 0; nt < 8; nt++)
            #pragma unroll
            for (int r = 0; r < 4; r++) {
                int c = nt * 8 + (lid & 3) * 2 + (r & 1);
                int v = wid * 32 + s * 16 + (lid >> 2) + ((r >> 1) << 3);
                Os[c * 396 + v] = oacc[s][nt][r];
            }
    __syncthreads();
    float* ob = out + ((size_t)(b * Cc) * Tt + t) * Vv;
    for (int c = wid; c < Cc; c += 12) {
        float* orow = ob + (size_t)c * Tt * Vv;
        for (int v = lid; v < Vv; v += 32)
            orow[v] = Os[c * 396 + v];
    }
}

extern "C" void kernel_launch(void* const* d_in, const int* in_sizes, int n_in,
                              void* d_out, int out_size)
{
    const float* x      = (const float*)d_in[0];
    const float* gso    = (const float*)d_in[1];
    const float* weight = (const float*)d_in[2];
    const float* bias   = (const float*)d_in[3];
    float* out = (float*)d_out;

    prep_gso<<<(NCHUNK * 384 * 24 + 255) / 256, 256>>>(gso);

    cudaFuncSetAttribute(gconv_hmma,
                         cudaFuncAttributeMaxDynamicSharedMemorySize, SM_TOTAL);
    gconv_hmma<<<32 * 64, TPB, SM_TOTAL>>>(x, gso, weight, bias, out);
}

// round 9
// speedup vs baseline: 3.4342x; 1.0039x over previous
#include <cuda_runtime.h>
#include <cuda_bf16.h>
#include <cstdint>

namespace {
constexpr int Cc = 64, Tt = 64, Vv = 325, TPB = 384;
constexpr int NCHUNK = 21;       // k16 chunks covering 325 (21*16 = 336, padded)
constexpr int BLK   = 36864;     // one 128-v block: X hi[128][72]+lo  (also hosts UT hi/lo)
constexpr int XLO   = 18432;     // lo offset within X block
constexpr int UTLO  = 17408;     // lo offset within UT block ([64][136] bf16 = 17408 B)
constexpr int GCH   = 24576;     // packed G chunk: [hi 384x32B][lo 384x32B]
constexpr int GLO   = 12288;     // lo half offset within G chunk
constexpr int GVALID = 10752;    // bytes actually copied per half (336 rows x 32B)
constexpr int SM_X  = 0;         // 3 blocks = 110592 B ; reused as Os[64][396] f32 in epilogue
constexpr int SM_W  = 110592;    // W1h,W1l,W0h,W0l each [64][72] bf16 = 9216 B
constexpr int SM_G  = 147456;    // 2 bufs x 24576, cp.async targets
constexpr int SM_BIAS = SM_G + 2 * GCH;      // 196608
constexpr int SM_TOTAL = SM_BIAS + 256;      // 196864 B
}

// Pre-converted gso, packed: per chunk [hi: 336x32B (+pad)][lo: 336x32B (+pad)]
__device__ __align__(16) unsigned char g_gso_bf16[NCHUNK * GCH];   // 516 KB

__device__ __forceinline__ uint32_t smem_u32(const void* p) {
    uint32_t a;
    asm("{ .reg .u64 tmp; cvta.to.shared.u64 tmp, %1; cvt.u32.u64 %0, tmp; }"
        : "=r"(a) : "l"(p));
    return a;
}
__device__ __forceinline__ void bsplit(float a, __nv_bfloat16& h, __nv_bfloat16& l) {
    h = __float2bfloat16(a);
    l = __float2bfloat16(a - __bfloat162float(h));
}
__device__ __forceinline__ void cpasync16(uint32_t dst, const void* src) {
    asm volatile("cp.async.cg.shared.global [%0], [%1], 16;"
                 :: "r"(dst), "l"(src) : "memory");
}
// copy one packed chunk (two 10752B spans); smem offsets == global offsets
__device__ __forceinline__ void copy_chunk(uint32_t dst, const unsigned char* src,
                                           int tid) {
    #pragma unroll
    for (int u = tid; u < 1344; u += TPB) {
        uint32_t off = (u < 672) ? (uint32_t)u * 16 : (uint32_t)(u - 672) * 16 + GLO;
        cpasync16(dst + off, src + off);
    }
}

#define LDSM4(r0, r1, r2, r3, addr)                                            \
    asm volatile("ldmatrix.sync.aligned.m8n8.x4.shared.b16 {%0,%1,%2,%3}, [%4];" \
                 : "=r"(r0), "=r"(r1), "=r"(r2), "=r"(r3) : "r"(addr))

#define MMA(d, a0, a1, a2, a3, b0, b1)                                         \
    asm volatile("mma.sync.aligned.m16n8k16.row.col.f32.bf16.bf16.f32 "        \
                 "{%0,%1,%2,%3},{%4,%5,%6,%7},{%8,%9},{%0,%1,%2,%3};"          \
                 : "+f"((d)[0]), "+f"((d)[1]), "+f"((d)[2]), "+f"((d)[3])      \
                 : "r"(a0), "r"(a1), "r"(a2), "r"(a3), "r"(b0), "r"(b1))

// ---------------- prepass: gso f32 -> packed bf16 hi/lo chunk images ----------------
__global__ void prep_gso(const float* __restrict__ gso)
{
    int idx = blockIdx.x * blockDim.x + threadIdx.x;     // NCHUNK*336*16
    if (idx >= NCHUNK * 336 * 16) return;
    int kk = idx / (336 * 16);
    int r  = (idx / 16) % 336;
    int c  = idx & 15;
    int kg = kk * 16 + c;
    float val = (r < Vv && kg < Vv) ? gso[(size_t)r * Vv + kg] : 0.0f;
    __nv_bfloat16 h, l;
    bsplit(val, h, l);
    unsigned char* base = g_gso_bf16 + (size_t)kk * GCH;
    *(__nv_bfloat16*)(base + r * 32 + c * 2)       = h;
    *(__nv_bfloat16*)(base + GLO + r * 32 + c * 2) = l;
}

// ---------------- main kernel: 12 warps, 32 M-rows per warp ----------------
__global__ void __launch_bounds__(TPB, 1)
gconv_hmma(const float* __restrict__ x, const float* __restrict__ gso,
           const float* __restrict__ w, const float* __restrict__ bias,
           float* __restrict__ out)
{
    extern __shared__ unsigned char smem[];
    const uint32_t sb = smem_u32(smem);
    const int tid = threadIdx.x, wid = tid >> 5, lid = tid & 31;
    const int bt = blockIdx.x, b = bt >> 6, t = bt & 63;

    // ---- kick off chunk-0 gso copy immediately (overlaps X staging + phase 1) ----
    copy_chunk(sb + SM_G, g_gso_bf16, tid);
    asm volatile("cp.async.commit_group;" ::: "memory");

    // ---- zero the static tail rows (336-383) of both G buffers, both halves ----
    // (copies never touch these; they stay zero for the whole kernel)
    {
        uint4 z = make_uint4(0, 0, 0, 0);
        int u = tid;   // 384 x 16B = 4 regions x 96
        int region = u / 96, within = u % 96;
        uint32_t off = SM_G + (region >> 1) * GCH + (region & 1) * GLO +
                       GVALID + (uint32_t)within * 16;
        *(uint4*)(smem + off) = z;
    }

    // ---- bias -> smem ----
    if (tid < Cc) ((float*)(smem + SM_BIAS))[tid] = bias[tid];

    // ---- weights as B-operands [c][i] row-major (stride 72 bf16), hi/lo ----
    // out = xp @ W[0] + (gso@xp) @ W[1] + bias + x
    for (int e = tid; e < Cc * Cc; e += TPB) {
        int i = e >> 6, c = e & 63;
        float w1 = w[Cc * Cc + e];                     // gso path (U = X@W1)
        float w0 = w[e] + (i == c ? 1.0f : 0.0f);      // direct path + residual fold
        uint32_t off = (uint32_t)(c * 144 + i * 2);
        __nv_bfloat16 h, l;
        bsplit(w1, h, l);
        *(__nv_bfloat16*)(smem + SM_W + off)        = h;
        *(__nv_bfloat16*)(smem + SM_W + 9216 + off) = l;
        bsplit(w0, h, l);
        *(__nv_bfloat16*)(smem + SM_W + 18432 + off) = h;
        *(__nv_bfloat16*)(smem + SM_W + 27648 + off) = l;
    }

    // ---- X as A-operand [v][i] row-major (stride 72 bf16), hi/lo ----
    const float* xb = x + ((size_t)(b * Cc) * Tt + t) * Vv;
    #pragma unroll
    for (int ii = 0; ii < 6; ii++) {
        int i = wid + 12 * ii;
        if (i < Cc) {
            const float* xr = xb + (size_t)i * Tt * Vv;
            for (int v = lid; v < 384; v += 32) {
                float val = (v < Vv) ? xr[v] : 0.0f;
                uint32_t off = (uint32_t)((v >> 7) * BLK + (v & 127) * 144 + i * 2);
                __nv_bfloat16 h, l;
                bsplit(val, h, l);
                *(__nv_bfloat16*)(smem + SM_X + off)       = h;
                *(__nv_bfloat16*)(smem + SM_X + XLO + off) = l;
            }
        }
    }
    __syncthreads();

    // ---- persistent out accumulators (2 m16 subtiles/warp), init with bias ----
    const float* bsm = (const float*)(smem + SM_BIAS);
    float oacc[2][8][4];
    #pragma unroll
    for (int s = 0; s < 2; s++)
        #pragma unroll
        for (int nt = 0; nt < 8; nt++)
            #pragma unroll
            for (int r = 0; r < 4; r++)
                oacc[s][nt][r] = bsm[nt * 8 + (lid & 3) * 2 + (r & 1)];

    // ================= phase 1: U = X@W1 ; oacc = bias + X@W0' (single pass) =========
    float uacc[2][8][4] = {};
    {
        const uint32_t xa0 = sb + SM_X + (wid >> 2) * BLK +
                             ((wid & 3) * 32 + (lid & 15)) * 144 + (lid >> 4) * 16;
        #pragma unroll
        for (int k = 0; k < 4; k++) {
            uint32_t a[2][8];
            #pragma unroll
            for (int s = 0; s < 2; s++) {
                LDSM4(a[s][0], a[s][1], a[s][2], a[s][3], xa0 + s * 2304 + k * 32);
                LDSM4(a[s][4], a[s][5], a[s][6], a[s][7], xa0 + s * 2304 + XLO + k * 32);
            }
            #pragma unroll
            for (int np = 0; np < 4; np++) {
                const uint32_t wa = sb + SM_W +
                    (np * 16 + (lid & 15)) * 144 + (lid >> 4) * 16 + k * 32;
                uint32_t h0, h1, h2, h3, l0, l1, l2, l3;
                LDSM4(h0, h1, h2, h3, wa);
                LDSM4(l0, l1, l2, l3, wa + 9216);
                #pragma unroll
                for (int s = 0; s < 2; s++) {
                    MMA(uacc[s][np * 2],     a[s][0], a[s][1], a[s][2], a[s][3], h0, h2);
                    MMA(uacc[s][np * 2],     a[s][0], a[s][1], a[s][2], a[s][3], l0, l2);
                    MMA(uacc[s][np * 2],     a[s][4], a[s][5], a[s][6], a[s][7], h0, h2);
                    MMA(uacc[s][np * 2 + 1], a[s][0], a[s][1], a[s][2], a[s][3], h1, h3);
                    MMA(uacc[s][np * 2 + 1], a[s][0], a[s][1], a[s][2], a[s][3], l1, l3);
                    MMA(uacc[s][np * 2 + 1], a[s][4], a[s][5], a[s][6], a[s][7], h1, h3);
                }
                LDSM4(h0, h1, h2, h3, wa + 18432);
                LDSM4(l0, l1, l2, l3, wa + 27648);
                #pragma unroll
                for (int s = 0; s < 2; s++) {
                    MMA(oacc[s][np * 2],     a[s][0], a[s][1], a[s][2], a[s][3], h0, h2);
                    MMA(oacc[s][np * 2],     a[s][0], a[s][1], a[s][2], a[s][3], l0, l2);
                    MMA(oacc[s][np * 2],     a[s][4], a[s][5], a[s][6], a[s][7], h0, h2);
                    MMA(oacc[s][np * 2 + 1], a[s][0], a[s][1], a[s][2], a[s][3], h1, h3);
                    MMA(oacc[s][np * 2 + 1], a[s][0], a[s][1], a[s][2], a[s][3], l1, l3);
                    MMA(oacc[s][np * 2 + 1], a[s][4], a[s][5], a[s][6], a[s][7], h1, h3);
                }
            }
        }
    }
    __syncthreads();   // all warps done reading X
    // write UT: [c][k'] stride 272B per 128-block; kp stays in warp's own block
    #pragma unroll
    for (int s = 0; s < 2; s++)
        #pragma unroll
        for (int nt = 0; nt < 8; nt++)
            #pragma unroll
            for (int r = 0; r < 4; r++) {
                int c  = nt * 8 + (lid & 3) * 2 + (r & 1);
                int kp = wid * 32 + s * 16 + (lid >> 2) + ((r >> 1) << 3);
                uint32_t off = (uint32_t)((kp >> 7) * BLK + c * 272 + (kp & 127) * 2);
                __nv_bfloat16 h, l;
                bsplit(uacc[s][nt][r], h, l);
                *(__nv_bfloat16*)(smem + SM_X + off)        = h;
                *(__nv_bfloat16*)(smem + SM_X + UTLO + off) = l;
            }

    // wait for chunk-0 gso copy, make UT + G + tail-zeros visible
    asm volatile("cp.async.wait_group 0;" ::: "memory");
    __syncthreads();

    // ================= phase 2: oacc += G @ U, cp.async pipelined =================
    for (int kk = 0; kk < NCHUNK; kk++) {
        if (kk < NCHUNK - 1) {   // issue next chunk's copy before this chunk's MMAs
            copy_chunk(sb + SM_G + ((kk + 1) & 1) * GCH,
                       g_gso_bf16 + (size_t)(kk + 1) * GCH, tid);
            asm volatile("cp.async.commit_group;" ::: "memory");
        }

        const uint32_t gb = sb + SM_G + (kk & 1) * GCH;
        const uint32_t ub = sb + SM_X + (kk >> 3) * BLK + (kk & 7) * 32;

        // load U B-fragments once, reuse for both m-subtiles
        uint32_t uf[4][8];
        #pragma unroll
        for (int np = 0; np < 4; np++) {
            const uint32_t ua = ub + (np * 16 + (lid & 15)) * 272 + (lid >> 4) * 16;
            LDSM4(uf[np][0], uf[np][1], uf[np][2], uf[np][3], ua);
            LDSM4(uf[np][4], uf[np][5], uf[np][6], uf[np][7], ua + UTLO);
        }
        #pragma unroll
        for (int s = 0; s < 2; s++) {
            const uint32_t ga = gb + (wid * 32 + s * 16 + (lid & 15)) * 32 +
                                (lid >> 4) * 16;
            uint32_t aH0, aH1, aH2, aH3, aL0, aL1, aL2, aL3;
            LDSM4(aH0, aH1, aH2, aH3, ga);
            LDSM4(aL0, aL1, aL2, aL3, ga + GLO);
            #pragma unroll
            for (int np = 0; np < 4; np++) {
                MMA(oacc[s][np * 2],     aH0, aH1, aH2, aH3, uf[np][0], uf[np][2]);
                MMA(oacc[s][np * 2],     aH0, aH1, aH2, aH3, uf[np][4], uf[np][6]);
                MMA(oacc[s][np * 2],     aL0, aL1, aL2, aL3, uf[np][0], uf[np][2]);
                MMA(oacc[s][np * 2 + 1], aH0, aH1, aH2, aH3, uf[np][1], uf[np][3]);
                MMA(oacc[s][np * 2 + 1], aH0, aH1, aH2, aH3, uf[np][5], uf[np][7]);
                MMA(oacc[s][np * 2 + 1], aL0, aL1, aL2, aL3, uf[np][1], uf[np][3]);
            }
        }

        if (kk < NCHUNK - 1) {
            asm volatile("cp.async.wait_group 0;" ::: "memory");
            __syncthreads();
        }
    }
    __syncthreads();

    // ================= epilogue: transpose via smem, coalesced [c][v] stores =========
    float* Os = (float*)(smem + SM_X);   // [64][396] f32, UT dead
    #pragma unroll
    for (int s = 0; s < 2; s++)
        #pragma unroll
        for (int nt = 0; nt < 8; nt++)
            #pragma unroll
            for (int r = 0; r < 4; r++) {
                int c = nt * 8 + (lid & 3) * 2 + (r & 1);
                int v = wid * 32 + s * 16 + (lid >> 2) + ((r >> 1) << 3);
                Os[c * 396 + v] = oacc[s][nt][r];
            }
    __syncthreads();
    float* ob = out + ((size_t)(b * Cc) * Tt + t) * Vv;
    for (int c = wid; c < Cc; c += 12) {
        float* orow = ob + (size_t)c * Tt * Vv;
        for (int v = lid; v < Vv; v += 32)
            orow[v] = Os[c * 396 + v];
    }
}

extern "C" void kernel_launch(void* const* d_in, const int* in_sizes, int n_in,
                              void* d_out, int out_size)
{
    const float* x      = (const float*)d_in[0];
    const float* gso    = (const float*)d_in[1];
    const float* weight = (const float*)d_in[2];
    const float* bias   = (const float*)d_in[3];
    float* out = (float*)d_out;

    prep_gso<<<(NCHUNK * 336 * 16 + 255) / 256, 256>>>(gso);

    cudaFuncSetAttribute(gconv_hmma,
                         cudaFuncAttributeMaxDynamicSharedMemorySize, SM_TOTAL);
    gconv_hmma<<<32 * 64, TPB, SM_TOTAL>>>(x, gso, weight, bias, out);
}

// round 10
// speedup vs baseline: 4.0281x; 1.1729x over previous
#include <cuda_runtime.h>
#include <cuda_fp16.h>
#include <cstdint>

namespace {
constexpr int Cc = 64, Tt = 64, Vv = 325, TPB = 384;
constexpr int NCHUNK = 21;       // k16 chunks covering 325 (21*16 = 336, padded)
constexpr int BLK   = 36864;     // one 128-v block: X hi[128][72]+lo  (also hosts UT hi/lo)
constexpr int XLO   = 18432;     // lo offset within X block
constexpr int UTLO  = 17408;     // lo offset within UT block ([64][136] fp16 = 17408 B)
constexpr int GCH   = 12288;     // packed G chunk, single fp16: 384x32B
constexpr int SM_X  = 0;         // 3 blocks = 110592 B ; reused as Os[64][396] f32 in epilogue
constexpr int SM_W  = 110592;    // W1h,W1l,W0h,W0l each [64][72] fp16 = 9216 B
constexpr int SM_G  = 147456;    // 2 bufs x 12288, cp.async targets
constexpr int SM_BIAS = SM_G + 2 * GCH;      // 172032
constexpr int SM_TOTAL = SM_BIAS + 256;      // 172288 B
}

// Pre-converted gso, packed single fp16: per chunk [336x32B valid (+tail pad)]
__device__ __align__(16) unsigned char g_gso_f16[NCHUNK * GCH];   // 258 KB

__device__ __forceinline__ uint32_t smem_u32(const void* p) {
    uint32_t a;
    asm("{ .reg .u64 tmp; cvta.to.shared.u64 tmp, %1; cvt.u32.u64 %0, tmp; }"
        : "=r"(a) : "l"(p));
    return a;
}
__device__ __forceinline__ void hsplit(float a, __half& h, __half& l) {
    h = __float2half_rn(a);
    l = __float2half_rn(a - __half2float(h));
}
__device__ __forceinline__ void cpasync16(uint32_t dst, const void* src) {
    asm volatile("cp.async.cg.shared.global [%0], [%1], 16;"
                 :: "r"(dst), "l"(src) : "memory");
}
// copy one packed chunk (672 x 16B = 10752B, rows 0-335); tail rows feed
// discarded v>=336 outputs, so they may hold garbage
__device__ __forceinline__ void copy_chunk(uint32_t dst, const unsigned char* src,
                                           int tid) {
    #pragma unroll
    for (int u = tid; u < 672; u += TPB)
        cpasync16(dst + (uint32_t)u * 16, src + (uint32_t)u * 16);
}

#define LDSM4(r0, r1, r2, r3, addr)                                            \
    asm volatile("ldmatrix.sync.aligned.m8n8.x4.shared.b16 {%0,%1,%2,%3}, [%4];" \
                 : "=r"(r0), "=r"(r1), "=r"(r2), "=r"(r3) : "r"(addr))

#define MMA(d, a0, a1, a2, a3, b0, b1)                                         \
    asm volatile("mma.sync.aligned.m16n8k16.row.col.f32.f16.f16.f32 "          \
                 "{%0,%1,%2,%3},{%4,%5,%6,%7},{%8,%9},{%0,%1,%2,%3};"          \
                 : "+f"((d)[0]), "+f"((d)[1]), "+f"((d)[2]), "+f"((d)[3])      \
                 : "r"(a0), "r"(a1), "r"(a2), "r"(a3), "r"(b0), "r"(b1))

// ---------------- prepass: gso f32 -> packed single-fp16 chunk images ----------------
__global__ void prep_gso(const float* __restrict__ gso)
{
    int idx = blockIdx.x * blockDim.x + threadIdx.x;     // NCHUNK*336*16
    if (idx >= NCHUNK * 336 * 16) return;
    int kk = idx / (336 * 16);
    int r  = (idx / 16) % 336;
    int c  = idx & 15;
    int kg = kk * 16 + c;
    float val = (r < Vv && kg < Vv) ? gso[(size_t)r * Vv + kg] : 0.0f;
    *(__half*)(g_gso_f16 + (size_t)kk * GCH + r * 32 + c * 2) = __float2half_rn(val);
}

// ---------------- main kernel: 12 warps, 32 M-rows per warp ----------------
__global__ void __launch_bounds__(TPB, 1)
gconv_hmma(const float* __restrict__ x, const float* __restrict__ gso,
           const float* __restrict__ w, const float* __restrict__ bias,
           float* __restrict__ out)
{
    extern __shared__ unsigned char smem[];
    const uint32_t sb = smem_u32(smem);
    const int tid = threadIdx.x, wid = tid >> 5, lid = tid & 31;
    const int bt = blockIdx.x, b = bt >> 6, t = bt & 63;

    // ---- kick off chunk-0 gso copy immediately (overlaps X staging + phase 1) ----
    copy_chunk(sb + SM_G, g_gso_f16, tid);
    asm volatile("cp.async.commit_group;" ::: "memory");

    // ---- bias -> smem ----
    if (tid < Cc) ((float*)(smem + SM_BIAS))[tid] = bias[tid];

    // ---- weights as B-operands [c][i] row-major (stride 72 fp16), hi/lo ----
    // out = xp @ W[0] + (gso@xp) @ W[1] + bias + x
    for (int e = tid; e < Cc * Cc; e += TPB) {
        int i = e >> 6, c = e & 63;
        float w1 = w[Cc * Cc + e];                     // gso path (U = X@W1)
        float w0 = w[e] + (i == c ? 1.0f : 0.0f);      // direct path + residual fold
        uint32_t off = (uint32_t)(c * 144 + i * 2);
        __half h, l;
        hsplit(w1, h, l);
        *(__half*)(smem + SM_W + off)        = h;
        *(__half*)(smem + SM_W + 9216 + off) = l;
        hsplit(w0, h, l);
        *(__half*)(smem + SM_W + 18432 + off) = h;
        *(__half*)(smem + SM_W + 27648 + off) = l;
    }

    // ---- X as A-operand [v][i] row-major (stride 72 fp16), hi/lo ----
    const float* xb = x + ((size_t)(b * Cc) * Tt + t) * Vv;
    #pragma unroll
    for (int ii = 0; ii < 6; ii++) {
        int i = wid + 12 * ii;
        if (i < Cc) {
            const float* xr = xb + (size_t)i * Tt * Vv;
            for (int v = lid; v < 384; v += 32) {
                float val = (v < Vv) ? xr[v] : 0.0f;
                uint32_t off = (uint32_t)((v >> 7) * BLK + (v & 127) * 144 + i * 2);
                __half h, l;
                hsplit(val, h, l);
                *(__half*)(smem + SM_X + off)       = h;
                *(__half*)(smem + SM_X + XLO + off) = l;
            }
        }
    }
    __syncthreads();

    // ---- persistent out accumulators (2 m16 subtiles/warp), init with bias ----
    const float* bsm = (const float*)(smem + SM_BIAS);
    float oacc[2][8][4];
    #pragma unroll
    for (int s = 0; s < 2; s++)
        #pragma unroll
        for (int nt = 0; nt < 8; nt++)
            #pragma unroll
            for (int r = 0; r < 4; r++)
                oacc[s][nt][r] = bsm[nt * 8 + (lid & 3) * 2 + (r & 1)];

    // ================= phase 1: U = X@W1 ; oacc = bias + X@W0' (single pass) =========
    // 2-term fp16 operands, 3-product structure: error ~2^-22
    float uacc[2][8][4] = {};
    {
        const uint32_t xa0 = sb + SM_X + (wid >> 2) * BLK +
                             ((wid & 3) * 32 + (lid & 15)) * 144 + (lid >> 4) * 16;
        #pragma unroll
        for (int k = 0; k < 4; k++) {
            uint32_t a[2][8];
            #pragma unroll
            for (int s = 0; s < 2; s++) {
                LDSM4(a[s][0], a[s][1], a[s][2], a[s][3], xa0 + s * 2304 + k * 32);
                LDSM4(a[s][4], a[s][5], a[s][6], a[s][7], xa0 + s * 2304 + XLO + k * 32);
            }
            #pragma unroll
            for (int np = 0; np < 4; np++) {
                const uint32_t wa = sb + SM_W +
                    (np * 16 + (lid & 15)) * 144 + (lid >> 4) * 16 + k * 32;
                uint32_t h0, h1, h2, h3, l0, l1, l2, l3;
                LDSM4(h0, h1, h2, h3, wa);
                LDSM4(l0, l1, l2, l3, wa + 9216);
                #pragma unroll
                for (int s = 0; s < 2; s++) {
                    MMA(uacc[s][np * 2],     a[s][0], a[s][1], a[s][2], a[s][3], h0, h2);
                    MMA(uacc[s][np * 2],     a[s][0], a[s][1], a[s][2], a[s][3], l0, l2);
                    MMA(uacc[s][np * 2],     a[s][4], a[s][5], a[s][6], a[s][7], h0, h2);
                    MMA(uacc[s][np * 2 + 1], a[s][0], a[s][1], a[s][2], a[s][3], h1, h3);
                    MMA(uacc[s][np * 2 + 1], a[s][0], a[s][1], a[s][2], a[s][3], l1, l3);
                    MMA(uacc[s][np * 2 + 1], a[s][4], a[s][5], a[s][6], a[s][7], h1, h3);
                }
                LDSM4(h0, h1, h2, h3, wa + 18432);
                LDSM4(l0, l1, l2, l3, wa + 27648);
                #pragma unroll
                for (int s = 0; s < 2; s++) {
                    MMA(oacc[s][np * 2],     a[s][0], a[s][1], a[s][2], a[s][3], h0, h2);
                    MMA(oacc[s][np * 2],     a[s][0], a[s][1], a[s][2], a[s][3], l0, l2);
                    MMA(oacc[s][np * 2],     a[s][4], a[s][5], a[s][6], a[s][7], h0, h2);
                    MMA(oacc[s][np * 2 + 1], a[s][0], a[s][1], a[s][2], a[s][3], h1, h3);
                    MMA(oacc[s][np * 2 + 1], a[s][0], a[s][1], a[s][2], a[s][3], l1, l3);
                    MMA(oacc[s][np * 2 + 1], a[s][4], a[s][5], a[s][6], a[s][7], h1, h3);
                }
            }
        }
    }
    __syncthreads();   // all warps done reading X
    // write UT: [c][k'] fp16 hi/lo, stride 272B per 128-block
    #pragma unroll
    for (int s = 0; s < 2; s++)
        #pragma unroll
        for (int nt = 0; nt < 8; nt++)
            #pragma unroll
            for (int r = 0; r < 4; r++) {
                int c  = nt * 8 + (lid & 3) * 2 + (r & 1);
                int kp = wid * 32 + s * 16 + (lid >> 2) + ((r >> 1) << 3);
                uint32_t off = (uint32_t)((kp >> 7) * BLK + c * 272 + (kp & 127) * 2);
                __half h, l;
                hsplit(uacc[s][nt][r], h, l);
                *(__half*)(smem + SM_X + off)        = h;
                *(__half*)(smem + SM_X + UTLO + off) = l;
            }

    // wait for chunk-0 gso copy, make UT + G visible
    asm volatile("cp.async.wait_group 0;" ::: "memory");
    __syncthreads();

    // ================= phase 2: oacc += G @ U (G single fp16), pipelined =============
    for (int kk = 0; kk < NCHUNK; kk++) {
        if (kk < NCHUNK - 1) {   // issue next chunk's copy before this chunk's MMAs
            copy_chunk(sb + SM_G + ((kk + 1) & 1) * GCH,
                       g_gso_f16 + (size_t)(kk + 1) * GCH, tid);
            asm volatile("cp.async.commit_group;" ::: "memory");
        }

        const uint32_t gb = sb + SM_G + (kk & 1) * GCH;
        const uint32_t ub = sb + SM_X + (kk >> 3) * BLK + (kk & 7) * 32;

        // load U B-fragments once, reuse for both m-subtiles
        uint32_t uf[4][8];
        #pragma unroll
        for (int np = 0; np < 4; np++) {
            const uint32_t ua = ub + (np * 16 + (lid & 15)) * 272 + (lid >> 4) * 16;
            LDSM4(uf[np][0], uf[np][1], uf[np][2], uf[np][3], ua);
            LDSM4(uf[np][4], uf[np][5], uf[np][6], uf[np][7], ua + UTLO);
        }
        #pragma unroll
        for (int s = 0; s < 2; s++) {
            const uint32_t ga = gb + (wid * 32 + s * 16 + (lid & 15)) * 32 +
                                (lid >> 4) * 16;
            uint32_t aH0, aH1, aH2, aH3;
            LDSM4(aH0, aH1, aH2, aH3, ga);
            #pragma unroll
            for (int np = 0; np < 4; np++) {
                MMA(oacc[s][np * 2],     aH0, aH1, aH2, aH3, uf[np][0], uf[np][2]);
                MMA(oacc[s][np * 2],     aH0, aH1, aH2, aH3, uf[np][4], uf[np][6]);
                MMA(oacc[s][np * 2 + 1], aH0, aH1, aH2, aH3, uf[np][1], uf[np][3]);
                MMA(oacc[s][np * 2 + 1], aH0, aH1, aH2, aH3, uf[np][5], uf[np][7]);
            }
        }

        if (kk < NCHUNK - 1) {
            asm volatile("cp.async.wait_group 0;" ::: "memory");
            __syncthreads();
        }
    }
    __syncthreads();

    // ================= epilogue: transpose via smem, coalesced [c][v] stores =========
    float* Os = (float*)(smem + SM_X);   // [64][396] f32, UT dead
    #pragma unroll
    for (int s = 0; s < 2; s++)
        #pragma unroll
        for (int nt = 0; nt < 8; nt++)
            #pragma unroll
            for (int r = 0; r < 4; r++) {
                int c = nt * 8 + (lid & 3) * 2 + (r & 1);
                int v = wid * 32 + s * 16 + (lid >> 2) + ((r >> 1) << 3);
                Os[c * 396 + v] = oacc[s][nt][r];
            }
    __syncthreads();
    float* ob = out + ((size_t)(b * Cc) * Tt + t) * Vv;
    for (int c = wid; c < Cc; c += 12) {
        float* orow = ob + (size_t)c * Tt * Vv;
        for (int v = lid; v < Vv; v += 32)
            orow[v] = Os[c * 396 + v];
    }
}

extern "C" void kernel_launch(void* const* d_in, const int* in_sizes, int n_in,
                              void* d_out, int out_size)
{
    const float* x      = (const float*)d_in[0];
    const float* gso    = (const float*)d_in[1];
    const float* weight = (const float*)d_in[2];
    const float* bias   = (const float*)d_in[3];
    float* out = (float*)d_out;

    prep_gso<<<(NCHUNK * 336 * 16 + 255) / 256, 256>>>(gso);

    cudaFuncSetAttribute(gconv_hmma,
                         cudaFuncAttributeMaxDynamicSharedMemorySize, SM_TOTAL);
    gconv_hmma<<<32 * 64, TPB, SM_TOTAL>>>(x, gso, weight, bias, out);
}

// round 11
// speedup vs baseline: 4.8643x; 1.2076x over previous
#include <cuda_runtime.h>
#include <cuda_fp16.h>
#include <cstdint>

namespace {
constexpr int Cc = 64, Tt = 64, Vv = 325, TPB = 384;
constexpr int NCHUNK = 21;       // k16 chunks covering 325 (21*16 = 336, padded)
constexpr int BLK   = 36864;     // one 128-v block: X hi[128][72]+lo  (also hosts UT)
constexpr int XLO   = 18432;     // lo offset within X block
constexpr int GCH   = 12288;     // packed G chunk, single fp16: 384x32B
constexpr int SM_X  = 0;         // 3 blocks = 110592 B ; reused as Os[64][396] f32
constexpr int SM_W  = 110592;    // W1h, W0h, W0l each [64][72] fp16 = 9216 B
constexpr int SM_G  = 110592 + 3 * 9216;     // 138240: 2 bufs x 12288
constexpr int SM_BIAS = SM_G + 2 * GCH;      // 162816
constexpr int SM_TOTAL = SM_BIAS + 256;      // 163072 B
}

// Pre-converted gso, packed single fp16: per chunk [336x32B valid (+tail pad)]
__device__ __align__(16) unsigned char g_gso_f16[NCHUNK * GCH];   // 258 KB

__device__ __forceinline__ uint32_t smem_u32(const void* p) {
    uint32_t a;
    asm("{ .reg .u64 tmp; cvta.to.shared.u64 tmp, %1; cvt.u32.u64 %0, tmp; }"
        : "=r"(a) : "l"(p));
    return a;
}
__device__ __forceinline__ void hsplit(float a, __half& h, __half& l) {
    h = __float2half_rn(a);
    l = __float2half_rn(a - __half2float(h));
}
__device__ __forceinline__ void cpasync16(uint32_t dst, const void* src) {
    asm volatile("cp.async.cg.shared.global [%0], [%1], 16;"
                 :: "r"(dst), "l"(src) : "memory");
}
// copy one packed chunk (672 x 16B = 10752B, rows 0-335); tail rows feed
// discarded v>=336 outputs, so they may hold garbage
__device__ __forceinline__ void copy_chunk(uint32_t dst, const unsigned char* src,
                                           int tid) {
    #pragma unroll
    for (int u = tid; u < 672; u += TPB)
        cpasync16(dst + (uint32_t)u * 16, src + (uint32_t)u * 16);
}

#define LDSM4(r0, r1, r2, r3, addr)                                            \
    asm volatile("ldmatrix.sync.aligned.m8n8.x4.shared.b16 {%0,%1,%2,%3}, [%4];" \
                 : "=r"(r0), "=r"(r1), "=r"(r2), "=r"(r3) : "r"(addr))

#define MMA(d, a0, a1, a2, a3, b0, b1)                                         \
    asm volatile("mma.sync.aligned.m16n8k16.row.col.f32.f16.f16.f32 "          \
                 "{%0,%1,%2,%3},{%4,%5,%6,%7},{%8,%9},{%0,%1,%2,%3};"          \
                 : "+f"((d)[0]), "+f"((d)[1]), "+f"((d)[2]), "+f"((d)[3])      \
                 : "r"(a0), "r"(a1), "r"(a2), "r"(a3), "r"(b0), "r"(b1))

// ---------------- prepass: gso f32 -> packed single-fp16 chunk images ----------------
__global__ void prep_gso(const float* __restrict__ gso)
{
    int idx = blockIdx.x * blockDim.x + threadIdx.x;     // NCHUNK*336*16
    if (idx >= NCHUNK * 336 * 16) return;
    int kk = idx / (336 * 16);
    int r  = (idx / 16) % 336;
    int c  = idx & 15;
    int kg = kk * 16 + c;
    float val = (r < Vv && kg < Vv) ? gso[(size_t)r * Vv + kg] : 0.0f;
    *(__half*)(g_gso_f16 + (size_t)kk * GCH + r * 32 + c * 2) = __float2half_rn(val);
}

// ---------------- main kernel: 12 warps, 32 M-rows per warp ----------------
__global__ void __launch_bounds__(TPB, 1)
gconv_hmma(const float* __restrict__ x, const float* __restrict__ gso,
           const float* __restrict__ w, const float* __restrict__ bias,
           float* __restrict__ out)
{
    extern __shared__ unsigned char smem[];
    const uint32_t sb = smem_u32(smem);
    const int tid = threadIdx.x, wid = tid >> 5, lid = tid & 31;
    const int bt = blockIdx.x, b = bt >> 6, t = bt & 63;

    // ---- kick off chunk-0 gso copy immediately (overlaps X staging + phase 1) ----
    copy_chunk(sb + SM_G, g_gso_f16, tid);
    asm volatile("cp.async.commit_group;" ::: "memory");

    // ---- bias -> smem ----
    if (tid < Cc) ((float*)(smem + SM_BIAS))[tid] = bias[tid];

    // ---- weights as B-operands [c][i] row-major (stride 72 fp16) ----
    // out = xp @ W[0] + (gso@xp) @ W[1] + bias + x
    // W1: hi only (U path is fp16-rounded anyway); W0': hi+lo (direct path precision)
    for (int e = tid; e < Cc * Cc; e += TPB) {
        int i = e >> 6, c = e & 63;
        float w1 = w[Cc * Cc + e];                     // gso path (U = X@W1)
        float w0 = w[e] + (i == c ? 1.0f : 0.0f);      // direct path + residual fold
        uint32_t off = (uint32_t)(c * 144 + i * 2);
        *(__half*)(smem + SM_W + off) = __float2half_rn(w1);
        __half h, l;
        hsplit(w0, h, l);
        *(__half*)(smem + SM_W + 9216 + off)  = h;
        *(__half*)(smem + SM_W + 18432 + off) = l;
    }

    // ---- X as A-operand [v][i] row-major (stride 72 fp16), hi/lo ----
    const float* xb = x + ((size_t)(b * Cc) * Tt + t) * Vv;
    #pragma unroll
    for (int ii = 0; ii < 6; ii++) {
        int i = wid + 12 * ii;
        if (i < Cc) {
            const float* xr = xb + (size_t)i * Tt * Vv;
            for (int v = lid; v < 384; v += 32) {
                float val = (v < Vv) ? xr[v] : 0.0f;
                uint32_t off = (uint32_t)((v >> 7) * BLK + (v & 127) * 144 + i * 2);
                __half h, l;
                hsplit(val, h, l);
                *(__half*)(smem + SM_X + off)       = h;
                *(__half*)(smem + SM_X + XLO + off) = l;
            }
        }
    }
    __syncthreads();

    // ---- persistent out accumulators (2 m16 subtiles/warp), init with bias ----
    const float* bsm = (const float*)(smem + SM_BIAS);
    float oacc[2][8][4];
    #pragma unroll
    for (int s = 0; s < 2; s++)
        #pragma unroll
        for (int nt = 0; nt < 8; nt++)
            #pragma unroll
            for (int r = 0; r < 4; r++)
                oacc[s][nt][r] = bsm[nt * 8 + (lid & 3) * 2 + (r & 1)];

    // ================= phase 1: U = X@W1 (2-term X, 1-term W1) ;
    //                            oacc = bias + X@W0' (2-term X, 2-term W0') =========
    float uacc[2][8][4] = {};
    {
        const uint32_t xa0 = sb + SM_X + (wid >> 2) * BLK +
                             ((wid & 3) * 32 + (lid & 15)) * 144 + (lid >> 4) * 16;
        #pragma unroll
        for (int k = 0; k < 4; k++) {
            uint32_t a[2][8];
            #pragma unroll
            for (int s = 0; s < 2; s++) {
                LDSM4(a[s][0], a[s][1], a[s][2], a[s][3], xa0 + s * 2304 + k * 32);
                LDSM4(a[s][4], a[s][5], a[s][6], a[s][7], xa0 + s * 2304 + XLO + k * 32);
            }
            #pragma unroll
            for (int np = 0; np < 4; np++) {
                const uint32_t wa = sb + SM_W +
                    (np * 16 + (lid & 15)) * 144 + (lid >> 4) * 16 + k * 32;
                uint32_t h0, h1, h2, h3, l0, l1, l2, l3;
                // W1 hi (U accumulation)
                LDSM4(h0, h1, h2, h3, wa);
                #pragma unroll
                for (int s = 0; s < 2; s++) {
                    MMA(uacc[s][np * 2],     a[s][0], a[s][1], a[s][2], a[s][3], h0, h2);
                    MMA(uacc[s][np * 2],     a[s][4], a[s][5], a[s][6], a[s][7], h0, h2);
                    MMA(uacc[s][np * 2 + 1], a[s][0], a[s][1], a[s][2], a[s][3], h1, h3);
                    MMA(uacc[s][np * 2 + 1], a[s][4], a[s][5], a[s][6], a[s][7], h1, h3);
                }
                // W0' hi/lo (out accumulation)
                LDSM4(h0, h1, h2, h3, wa + 9216);
                LDSM4(l0, l1, l2, l3, wa + 18432);
                #pragma unroll
                for (int s = 0; s < 2; s++) {
                    MMA(oacc[s][np * 2],     a[s][0], a[s][1], a[s][2], a[s][3], h0, h2);
                    MMA(oacc[s][np * 2],     a[s][0], a[s][1], a[s][2], a[s][3], l0, l2);
                    MMA(oacc[s][np * 2],     a[s][4], a[s][5], a[s][6], a[s][7], h0, h2);
                    MMA(oacc[s][np * 2 + 1], a[s][0], a[s][1], a[s][2], a[s][3], h1, h3);
                    MMA(oacc[s][np * 2 + 1], a[s][0], a[s][1], a[s][2], a[s][3], l1, l3);
                    MMA(oacc[s][np * 2 + 1], a[s][4], a[s][5], a[s][6], a[s][7], h1, h3);
                }
            }
        }
    }
    __syncthreads();   // all warps done reading X
    // write UT: [c][k'] single fp16, stride 272B per 128-block
    #pragma unroll
    for (int s = 0; s < 2; s++)
        #pragma unroll
        for (int nt = 0; nt < 8; nt++)
            #pragma unroll
            for (int r = 0; r < 4; r++) {
                int c  = nt * 8 + (lid & 3) * 2 + (r & 1);
                int kp = wid * 32 + s * 16 + (lid >> 2) + ((r >> 1) << 3);
                uint32_t off = (uint32_t)((kp >> 7) * BLK + c * 272 + (kp & 127) * 2);
                *(__half*)(smem + SM_X + off) = __float2half_rn(uacc[s][nt][r]);
            }

    // wait for chunk-0 gso copy, make UT + G visible
    asm volatile("cp.async.wait_group 0;" ::: "memory");
    __syncthreads();

    // ================= phase 2: oacc += G @ U (both single fp16), pipelined ==========
    for (int kk = 0; kk < NCHUNK; kk++) {
        if (kk < NCHUNK - 1) {   // issue next chunk's copy before this chunk's MMAs
            copy_chunk(sb + SM_G + ((kk + 1) & 1) * GCH,
                       g_gso_f16 + (size_t)(kk + 1) * GCH, tid);
            asm volatile("cp.async.commit_group;" ::: "memory");
        }

        const uint32_t gb = sb + SM_G + (kk & 1) * GCH;
        const uint32_t ub = sb + SM_X + (kk >> 3) * BLK + (kk & 7) * 32;

        // load U B-fragments once, reuse for both m-subtiles
        uint32_t uf[4][4];
        #pragma unroll
        for (int np = 0; np < 4; np++) {
            const uint32_t ua = ub + (np * 16 + (lid & 15)) * 272 + (lid >> 4) * 16;
            LDSM4(uf[np][0], uf[np][1], uf[np][2], uf[np][3], ua);
        }
        #pragma unroll
        for (int s = 0; s < 2; s++) {
            const uint32_t ga = gb + (wid * 32 + s * 16 + (lid & 15)) * 32 +
                                (lid >> 4) * 16;
            uint32_t aH0, aH1, aH2, aH3;
            LDSM4(aH0, aH1, aH2, aH3, ga);
            #pragma unroll
            for (int np = 0; np < 4; np++) {
                MMA(oacc[s][np * 2],     aH0, aH1, aH2, aH3, uf[np][0], uf[np][2]);
                MMA(oacc[s][np * 2 + 1], aH0, aH1, aH2, aH3, uf[np][1], uf[np][3]);
            }
        }

        if (kk < NCHUNK - 1) {
            asm volatile("cp.async.wait_group 0;" ::: "memory");
            __syncthreads();
        }
    }
    __syncthreads();

    // ================= epilogue: transpose via smem, coalesced [c][v] stores =========
    float* Os = (float*)(smem + SM_X);   // [64][396] f32, UT dead
    #pragma unroll
    for (int s = 0; s < 2; s++)
        #pragma unroll
        for (int nt = 0; nt < 8; nt++)
            #pragma unroll
            for (int r = 0; r < 4; r++) {
                int c = nt * 8 + (lid & 3) * 2 + (r & 1);
                int v = wid * 32 + s * 16 + (lid >> 2) + ((r >> 1) << 3);
                Os[c * 396 + v] = oacc[s][nt][r];
            }
    __syncthreads();
    float* ob = out + ((size_t)(b * Cc) * Tt + t) * Vv;
    for (int c = wid; c < Cc; c += 12) {
        float* orow = ob + (size_t)c * Tt * Vv;
        for (int v = lid; v < Vv; v += 32)
            orow[v] = Os[c * 396 + v];
    }
}

extern "C" void kernel_launch(void* const* d_in, const int* in_sizes, int n_in,
                              void* d_out, int out_size)
{
    const float* x      = (const float*)d_in[0];
    const float* gso    = (const float*)d_in[1];
    const float* weight = (const float*)d_in[2];
    const float* bias   = (const float*)d_in[3];
    float* out = (float*)d_out;

    prep_gso<<<(NCHUNK * 336 * 16 + 255) / 256, 256>>>(gso);

    cudaFuncSetAttribute(gconv_hmma,
                         cudaFuncAttributeMaxDynamicSharedMemorySize, SM_TOTAL);
    gconv_hmma<<<32 * 64, TPB, SM_TOTAL>>>(x, gso, weight, bias, out);
}

// round 13
// speedup vs baseline: 5.9097x; 1.2149x over previous
#include <cuda_runtime.h>
#include <cuda_fp16.h>
#include <cstdint>

namespace {
constexpr int Cc = 64, Tt = 64, Vv = 325, TPB = 384;
constexpr int NCHUNK = 11;       // k32 chunks covering 325 (11*32 = 352, padded)
constexpr int XBLK  = 18432;     // one 128-v block: X[128][72] fp16 (also hosts UT)
constexpr int GSTR  = 80;        // G row stride in bytes (16B-aligned for ldmatrix)
constexpr int GCH   = 384 * GSTR;            // 30720 per chunk buffer
constexpr int SM_X  = 0;         // 3 blocks = 55296 ; reused as Os[64][396] f32
constexpr int SM_W  = 55296;     // W1h, W0h each [64][72] fp16 = 9216 B
constexpr int SM_G  = 55296 + 2 * 9216;      // 73728: 2 bufs x 30720
constexpr int SM_BIAS = SM_G + 2 * GCH;      // 135168
constexpr int SM_TOTAL = SM_BIAS + 256;      // 135424 B
}

// Pre-converted gso, fp16: per chunk [336 rows x 32 k] at 80B row stride
__device__ __align__(16) unsigned char g_gso_f16[NCHUNK * GCH];   // ~338 KB

__device__ __forceinline__ uint32_t smem_u32(const void* p) {
    uint32_t a;
    asm("{ .reg .u64 tmp; cvta.to.shared.u64 tmp, %1; cvt.u32.u64 %0, tmp; }"
        : "=r"(a) : "l"(p));
    return a;
}
__device__ __forceinline__ void cpasync16(uint32_t dst, const void* src) {
    asm volatile("cp.async.cg.shared.global [%0], [%1], 16;"
                 :: "r"(dst), "l"(src) : "memory");
}
// copy one chunk: 1680 x 16B = 26880 B (rows 0-335; rows >=336 stale = discarded v)
__device__ __forceinline__ void copy_chunk(uint32_t dst, const unsigned char* src,
                                           int tid) {
    #pragma unroll
    for (int u = tid; u < 1680; u += TPB)
        cpasync16(dst + (uint32_t)u * 16, src + (uint32_t)u * 16);
}

#define LDSM4(r0, r1, r2, r3, addr)                                            \
    asm volatile("ldmatrix.sync.aligned.m8n8.x4.shared.b16 {%0,%1,%2,%3}, [%4];" \
                 : "=r"(r0), "=r"(r1), "=r"(r2), "=r"(r3) : "r"(addr))

#define MMA(d, a0, a1, a2, a3, b0, b1)                                         \
    asm volatile("mma.sync.aligned.m16n8k16.row.col.f32.f16.f16.f32 "          \
                 "{%0,%1,%2,%3},{%4,%5,%6,%7},{%8,%9},{%0,%1,%2,%3};"          \
                 : "+f"((d)[0]), "+f"((d)[1]), "+f"((d)[2]), "+f"((d)[3])      \
                 : "r"(a0), "r"(a1), "r"(a2), "r"(a3), "r"(b0), "r"(b1))

// ---------------- prepass: gso f32 -> fp16 k32-chunk images (80B rows) ------------
__global__ void prep_gso(const float* __restrict__ gso)
{
    int idx = blockIdx.x * blockDim.x + threadIdx.x;     // NCHUNK*336*32
    if (idx >= NCHUNK * 336 * 32) return;
    int kk = idx / (336 * 32);
    int r  = (idx / 32) % 336;
    int c  = idx & 31;
    int kg = kk * 32 + c;
    float val = (r < Vv && kg < Vv) ? gso[(size_t)r * Vv + kg] : 0.0f;
    *(__half*)(g_gso_f16 + (size_t)kk * GCH + r * GSTR + c * 2) = __float2half_rn(val);
}

// ---------------- main kernel: 12 warps, 32 M-rows per warp ----------------
__global__ void __launch_bounds__(TPB, 1)
gconv_hmma(const float* __restrict__ x, const float* __restrict__ gso,
           const float* __restrict__ w, const float* __restrict__ bias,
           float* __restrict__ out)
{
    extern __shared__ unsigned char smem[];
    const uint32_t sb = smem_u32(smem);
    const int tid = threadIdx.x, wid = tid >> 5, lid = tid & 31;
    const int bt = blockIdx.x, b = bt >> 6, t = bt & 63;

    // ---- kick off chunk-0 gso copy immediately (overlaps X staging + phase 1) ----
    copy_chunk(sb + SM_G, g_gso_f16, tid);
    asm volatile("cp.async.commit_group;" ::: "memory");

    // ---- bias -> smem ----
    if (tid < Cc) ((float*)(smem + SM_BIAS))[tid] = bias[tid];

    // ---- weights as B-operands [c][i] row-major (stride 72 fp16), single term ----
    // out = xp @ W[0] + (gso@xp) @ W[1] + bias + x
    for (int e = tid; e < Cc * Cc; e += TPB) {
        int i = e >> 6, c = e & 63;
        float w1 = w[Cc * Cc + e];                     // gso path (U = X@W1)
        float w0 = w[e] + (i == c ? 1.0f : 0.0f);      // direct path + residual fold
        uint32_t off = (uint32_t)(c * 144 + i * 2);
        *(__half*)(smem + SM_W + off)        = __float2half_rn(w1);
        *(__half*)(smem + SM_W + 9216 + off) = __float2half_rn(w0);
    }

    // ---- X as A-operand [v][i] row-major (stride 72 fp16), single term ----
    const float* xb = x + ((size_t)(b * Cc) * Tt + t) * Vv;
    #pragma unroll
    for (int ii = 0; ii < 6; ii++) {
        int i = wid + 12 * ii;
        if (i < Cc) {
            const float* xr = xb + (size_t)i * Tt * Vv;
            for (int v = lid; v < 384; v += 32) {
                float val = (v < Vv) ? xr[v] : 0.0f;
                uint32_t off = (uint32_t)((v >> 7) * XBLK + (v & 127) * 144 + i * 2);
                *(__half*)(smem + SM_X + off) = __float2half_rn(val);
            }
        }
    }
    __syncthreads();

    // ---- persistent out accumulators (2 m16 subtiles/warp), init with bias ----
    const float* bsm = (const float*)(smem + SM_BIAS);
    float oacc[2][8][4];
    #pragma unroll
    for (int s = 0; s < 2; s++)
        #pragma unroll
        for (int nt = 0; nt < 8; nt++)
            #pragma unroll
            for (int r = 0; r < 4; r++)
                oacc[s][nt][r] = bsm[nt * 8 + (lid & 3) * 2 + (r & 1)];

    // ================= phase 1: U = X@W1 ; oacc = bias + X@W0' (all single fp16) =====
    float uacc[2][8][4] = {};
    {
        const uint32_t xa0 = sb + SM_X + (wid >> 2) * XBLK +
                             ((wid & 3) * 32 + (lid & 15)) * 144 + (lid >> 4) * 16;
        #pragma unroll
        for (int k = 0; k < 4; k++) {
            uint32_t a[2][4];
            #pragma unroll
            for (int s = 0; s < 2; s++)
                LDSM4(a[s][0], a[s][1], a[s][2], a[s][3], xa0 + s * 2304 + k * 32);
            #pragma unroll
            for (int np = 0; np < 4; np++) {
                const uint32_t wa = sb + SM_W +
                    (np * 16 + (lid & 15)) * 144 + (lid >> 4) * 16 + k * 32;
                uint32_t h0, h1, h2, h3, g0, g1, g2, g3;
                LDSM4(h0, h1, h2, h3, wa);            // W1
                LDSM4(g0, g1, g2, g3, wa + 9216);     // W0'
                #pragma unroll
                for (int s = 0; s < 2; s++) {
                    MMA(uacc[s][np * 2],     a[s][0], a[s][1], a[s][2], a[s][3], h0, h2);
                    MMA(uacc[s][np * 2 + 1], a[s][0], a[s][1], a[s][2], a[s][3], h1, h3);
                    MMA(oacc[s][np * 2],     a[s][0], a[s][1], a[s][2], a[s][3], g0, g2);
                    MMA(oacc[s][np * 2 + 1], a[s][0], a[s][1], a[s][2], a[s][3], g1, g3);
                }
            }
        }
    }
    __syncthreads();   // all warps done reading X
    // write UT: [c][k'] single fp16, stride 272B per 128-block
    #pragma unroll
    for (int s = 0; s < 2; s++)
        #pragma unroll
        for (int nt = 0; nt < 8; nt++)
            #pragma unroll
            for (int r = 0; r < 4; r++) {
                int c  = nt * 8 + (lid & 3) * 2 + (r & 1);
                int kp = wid * 32 + s * 16 + (lid >> 2) + ((r >> 1) << 3);
                uint32_t off = (uint32_t)((kp >> 7) * XBLK + c * 272 + (kp & 127) * 2);
                *(__half*)(smem + SM_X + off) = __float2half_rn(uacc[s][nt][r]);
            }

    // wait for chunk-0 gso copy, make UT + G visible
    asm volatile("cp.async.wait_group 0;" ::: "memory");
    __syncthreads();

    // ================= phase 2: oacc += G @ U, k32 chunks, pipelined =================
    for (int kk = 0; kk < NCHUNK; kk++) {
        if (kk < NCHUNK - 1) {   // issue next chunk's copy before this chunk's MMAs
            copy_chunk(sb + SM_G + ((kk + 1) & 1) * GCH,
                       g_gso_f16 + (size_t)(kk + 1) * GCH, tid);
            asm volatile("cp.async.commit_group;" ::: "memory");
        }

        const uint32_t gb = sb + SM_G + (kk & 1) * GCH;
        const uint32_t ub = sb + SM_X + (kk >> 2) * XBLK + (kk & 3) * 64;

        // load U B-fragments once (both k16 halves), reuse for both m-subtiles
        uint32_t uf[4][2][4];
        #pragma unroll
        for (int np = 0; np < 4; np++) {
            const uint32_t ua = ub + (np * 16 + (lid & 15)) * 272 + (lid >> 4) * 16;
            LDSM4(uf[np][0][0], uf[np][0][1], uf[np][0][2], uf[np][0][3], ua);
            LDSM4(uf[np][1][0], uf[np][1][1], uf[np][1][2], uf[np][1][3], ua + 32);
        }
        #pragma unroll
        for (int s = 0; s < 2; s++) {
            const uint32_t ga = gb + (wid * 32 + s * 16 + (lid & 15)) * GSTR +
                                (lid >> 4) * 16;
            #pragma unroll
            for (int ks = 0; ks < 2; ks++) {
                uint32_t a0, a1, a2, a3;
                LDSM4(a0, a1, a2, a3, ga + ks * 32);
                #pragma unroll
                for (int np = 0; np < 4; np++) {
                    MMA(oacc[s][np * 2],     a0, a1, a2, a3, uf[np][ks][0], uf[np][ks][2]);
                    MMA(oacc[s][np * 2 + 1], a0, a1, a2, a3, uf[np][ks][1], uf[np][ks][3]);
                }
            }
        }

        if (kk < NCHUNK - 1) {
            asm volatile("cp.async.wait_group 0;" ::: "memory");
            __syncthreads();
        }
    }
    __syncthreads();

    // ================= epilogue: transpose via smem, coalesced [c][v] stores =========
    float* Os = (float*)(smem + SM_X);   // [64][396] f32, UT/W/G dead
    #pragma unroll
    for (int s = 0; s < 2; s++)
        #pragma unroll
        for (int nt = 0; nt < 8; nt++)
            #pragma unroll
            for (int r = 0; r < 4; r++) {
                int c = nt * 8 + (lid & 3) * 2 + (r & 1);
                int v = wid * 32 + s * 16 + (lid >> 2) + ((r >> 1) << 3);
                Os[c * 396 + v] = oacc[s][nt][r];
            }
    __syncthreads();
    float* ob = out + ((size_t)(b * Cc) * Tt + t) * Vv;
    for (int c = wid; c < Cc; c += 12) {
        float* orow = ob + (size_t)c * Tt * Vv;
        for (int v = lid; v < Vv; v += 32)
            orow[v] = Os[c * 396 + v];
    }
}

extern "C" void kernel_launch(void* const* d_in, const int* in_sizes, int n_in,
                              void* d_out, int out_size)
{
    const float* x      = (const float*)d_in[0];
    const float* gso    = (const float*)d_in[1];
    const float* weight = (const float*)d_in[2];
    const float* bias   = (const float*)d_in[3];
    float* out = (float*)d_out;

    prep_gso<<<(NCHUNK * 336 * 32 + 255) / 256, 256>>>(gso);

    cudaFuncSetAttribute(gconv_hmma,
                         cudaFuncAttributeMaxDynamicSharedMemorySize, SM_TOTAL);
    gconv_hmma<<<32 * 64, TPB, SM_TOTAL>>>(x, gso, weight, bias, out);
}